// round 7
// baseline (speedup 1.0000x reference)
#include <cuda_runtime.h>
#include <cuda_bf16.h>
#include <cuda_fp16.h>
#include <math.h>
#include <stdint.h>

// Problem constants
#define SS 1024   // sequence length S
#define BB 32     // batch B
#define DD 1024   // model dim D

// Scratch (device globals — allocation-guard-safe)
__device__ __half g_probH[(size_t)BB * SS * SS];   // (B, S, S) fp16
__device__ __half g_peT[(size_t)BB * DD * SS];     // (B, D, S) fp16
__device__ float g_pred[SS * BB];
__device__ float g_valid[BB * SS];
__device__ float g_slen[BB];
__device__ float g_lang[BB];
__device__ int   g_mask_is_i32;

// ---------------------------------------------------------------------------
// K-1: sniff the mask dtype (bool delivered as uint8 or int32).
// ---------------------------------------------------------------------------
__global__ void sniff_kernel(const int* __restrict__ m) {
    __shared__ int bad[256];
    int tid = threadIdx.x;
    int any = 0;
#pragma unroll
    for (int t = 0; t < 32; t++) {
        int v = m[t * 256 + tid];
        any |= ((unsigned)v > 1u) ? 1 : 0;
    }
    bad[tid] = any;
    __syncthreads();
    if (tid == 0) {
        int a = 0;
        for (int k = 0; k < 256; k++) a |= bad[k];
        g_mask_is_i32 = a ? 0 : 1;
    }
}

// ---------------------------------------------------------------------------
// K0: expand mask + per-batch reduction.
// ---------------------------------------------------------------------------
__global__ __launch_bounds__(1024) void mask_kernel(const void* __restrict__ maskp) {
    int b = blockIdx.x;
    int j = threadIdx.x;

    int mv;
    if (g_mask_is_i32) mv = ((const int*)maskp)[b * SS + j];
    else               mv = ((const unsigned char*)maskp)[b * SS + j];

    float valid = (mv == 0) ? 1.0f : 0.0f;
    g_valid[b * SS + j] = valid;

    __shared__ float red[32];
    float c = valid;
#pragma unroll
    for (int o = 16; o; o >>= 1) c += __shfl_xor_sync(0xFFFFFFFFu, c, o);
    if ((j & 31) == 0) red[j >> 5] = c;
    __syncthreads();
    if (j == 0) {
        float s = 0.0f;
#pragma unroll
        for (int w = 0; w < 32; w++) s += red[w];
        g_slen[b] = s;
        g_lang[b] = (float)SS - s;
    }
}

// ---------------------------------------------------------------------------
// K1: pred[i,b] = sigmoid(x[i,b,:]·W + bias) * slen[b].  One warp per (i,b).
// ---------------------------------------------------------------------------
__global__ __launch_bounds__(256) void pred_kernel(
    const float* __restrict__ x, const float* __restrict__ W,
    const float* __restrict__ bias)
{
    int warp = (blockIdx.x * blockDim.x + threadIdx.x) >> 5;
    int lane = threadIdx.x & 31;
    int i = warp >> 5;
    int b = warp & 31;

    const float4* xv = (const float4*)(x + ((size_t)i * BB + b) * DD);
    const float4* wv = (const float4*)W;
    float sum = 0.0f;
#pragma unroll
    for (int t = 0; t < 8; t++) {
        float4 a = xv[t * 32 + lane];
        float4 w = wv[t * 32 + lane];
        sum += a.x * w.x + a.y * w.y + a.z * w.z + a.w * w.w;
    }
#pragma unroll
    for (int o = 16; o; o >>= 1) sum += __shfl_xor_sync(0xFFFFFFFFu, sum, o);
    if (lane == 0) {
        float t = sum + bias[0];
        float p = 1.0f / (1.0f + expf(-t));
        g_pred[i * BB + b] = p * g_slen[b];
    }
}

// ---------------------------------------------------------------------------
// K2: normalized, gated prob row -> fp16, stored (B, S, S).
// ---------------------------------------------------------------------------
__global__ __launch_bounds__(256) void prob_kernel() {
    int i = blockIdx.x;
    int b = blockIdx.y;
    int tid = threadIdx.x;

    float pr   = g_pred[i * BB + b];
    float lang = g_lang[b];
    const float* vrow = g_valid + b * SS;

    float v[4];
    float lsum = 0.0f;
#pragma unroll
    for (int t = 0; t < 4; t++) {
        int j = tid + t * 256;
        float d   = pr - ((float)j - lang);
        float val = vrow[j] / (d * d + 0.001f);
        v[t] = val;
        lsum += val;
    }

    __shared__ float red[8];
#pragma unroll
    for (int o = 16; o; o >>= 1) lsum += __shfl_xor_sync(0xFFFFFFFFu, lsum, o);
    if ((tid & 31) == 0) red[tid >> 5] = lsum;
    __syncthreads();
    if (tid == 0) {
        float s = 0.0f;
#pragma unroll
        for (int w = 0; w < 8; w++) s += red[w];
        red[0] = (s > 0.0f) ? (vrow[i] / s) : 0.0f;
    }
    __syncthreads();
    float scale = red[0];

    size_t base = ((size_t)b * SS + i) * SS;
#pragma unroll
    for (int t = 0; t < 4; t++) {
        int j = tid + t * 256;
        g_probH[base + j] = __float2half_rn(v[t] * scale);
    }
}

// ---------------------------------------------------------------------------
// K2b: transpose pe (S,B,D) -> peT (B,D,S) fp16. 64x64 tile per block.
// ---------------------------------------------------------------------------
__global__ __launch_bounds__(256) void transpose_kernel(const float* __restrict__ pe) {
    __shared__ float t[64][65];
    int j0 = blockIdx.x * 64;
    int d0 = blockIdx.y * 64;
    int b  = blockIdx.z;
    int tid = threadIdx.x;

#pragma unroll
    for (int q = 0; q < 4; q++) {
        int idx = tid + 256 * q;          // 0..1023
        int jr  = idx >> 4;               // 0..63
        int c4  = idx & 15;
        float4 v = *(const float4*)(pe + ((size_t)(j0 + jr) * BB + b) * DD + d0 + c4 * 4);
        t[jr][c4 * 4 + 0] = v.x;
        t[jr][c4 * 4 + 1] = v.y;
        t[jr][c4 * 4 + 2] = v.z;
        t[jr][c4 * 4 + 3] = v.w;
    }
    __syncthreads();

#pragma unroll
    for (int q = 0; q < 4; q++) {
        int idx = tid + 256 * q;
        int dr  = idx >> 4;               // 0..63
        int c4  = idx & 15;               // 4 j's
        __half h[4];
#pragma unroll
        for (int k = 0; k < 4; k++) h[k] = __float2half_rn(t[c4 * 4 + k][dr]);
        size_t dst = ((size_t)b * DD + d0 + dr) * SS + j0 + c4 * 4;
        *(uint2*)&g_peT[dst] = *(uint2*)h;
    }
}

// ---------------------------------------------------------------------------
// K3: batched GEMM via fp16 mma.sync m16n8k16 (fp32 accumulate).
// Per batch b: OUT[i,d] = sum_j probH[b,i,j] * peT[b,d,j]
// Block tile 128x128, BK=32. 256 threads = 8 warps (2 m x 4 n), warp tile 64x32.
// Both operands K-major in smem; fragment reg pairs are contiguous 4B LDS.
// Single-buffer smem + register prefetch of next K tile.
// ---------------------------------------------------------------------------
#define AST 40   // padded smem row stride in halves (80B, 16B-aligned, bank-clean)

__global__ __launch_bounds__(256) void gemm_fp16_kernel(float* __restrict__ out) {
    const int b  = blockIdx.z;
    const int ti = blockIdx.y * 128;  // output row tile (i)
    const int td = blockIdx.x * 128;  // output col tile (d)

    __shared__ __half As[128 * AST];  // (m, k)
    __shared__ __half Bs[128 * AST];  // (n, k)

    const int tid  = threadIdx.x;
    const int lane = tid & 31;
    const int warp = tid >> 5;
    const int wm   = warp & 1;        // 0..1  (m)
    const int wn   = warp >> 1;       // 0..3  (n)
    const int gid  = lane >> 2;       // 0..7
    const int tig  = lane & 3;        // 0..3

    // Global->smem mapping: idx = tid + 256*t (t=0..1); row = idx>>2 (0..127),
    // q = idx&3 -> 8-half (16B) chunk within the 32-half row.
    const int grow = tid >> 2;
    const int gq   = (tid & 3) * 8;

    const __half* Ab = g_probH + ((size_t)b * SS + ti) * SS;
    const __half* Bb = g_peT   + ((size_t)b * DD + td) * SS;

    float acc[4][4][4];
#pragma unroll
    for (int mf = 0; mf < 4; mf++)
#pragma unroll
        for (int nf = 0; nf < 4; nf++)
#pragma unroll
            for (int r = 0; r < 4; r++) acc[mf][nf][r] = 0.0f;

    uint4 pa[2], pb[2];

    // Prefetch first K tile (k0 = 0)
#pragma unroll
    for (int t = 0; t < 2; t++) {
        pa[t] = *(const uint4*)(Ab + (size_t)(grow + 64 * t) * SS + gq);
        pb[t] = *(const uint4*)(Bb + (size_t)(grow + 64 * t) * SS + gq);
    }

    const int NK = SS / 32;
    for (int kt = 0; kt < NK; kt++) {
        __syncthreads();

#pragma unroll
        for (int t = 0; t < 2; t++) {
            *(uint4*)&As[(grow + 64 * t) * AST + gq] = pa[t];
            *(uint4*)&Bs[(grow + 64 * t) * AST + gq] = pb[t];
        }
        __syncthreads();

        if (kt + 1 < NK) {
            int k0 = (kt + 1) * 32;
#pragma unroll
            for (int t = 0; t < 2; t++) {
                pa[t] = *(const uint4*)(Ab + (size_t)(grow + 64 * t) * SS + k0 + gq);
                pb[t] = *(const uint4*)(Bb + (size_t)(grow + 64 * t) * SS + k0 + gq);
            }
        }

        // Compute: 2 k-steps of m16n8k16
#pragma unroll
        for (int ks = 0; ks < 32; ks += 16) {
            uint32_t afr[4][4];
#pragma unroll
            for (int mf = 0; mf < 4; mf++) {
                int r0 = wm * 64 + mf * 16 + gid;
                afr[mf][0] = *(const uint32_t*)&As[(r0    ) * AST + ks + tig * 2    ];
                afr[mf][1] = *(const uint32_t*)&As[(r0 + 8) * AST + ks + tig * 2    ];
                afr[mf][2] = *(const uint32_t*)&As[(r0    ) * AST + ks + tig * 2 + 8];
                afr[mf][3] = *(const uint32_t*)&As[(r0 + 8) * AST + ks + tig * 2 + 8];
            }
            uint32_t bfr[4][2];
#pragma unroll
            for (int nf = 0; nf < 4; nf++) {
                int c0 = wn * 32 + nf * 8 + gid;
                bfr[nf][0] = *(const uint32_t*)&Bs[c0 * AST + ks + tig * 2    ];
                bfr[nf][1] = *(const uint32_t*)&Bs[c0 * AST + ks + tig * 2 + 8];
            }
#pragma unroll
            for (int mf = 0; mf < 4; mf++) {
#pragma unroll
                for (int nf = 0; nf < 4; nf++) {
                    asm volatile(
                        "mma.sync.aligned.m16n8k16.row.col.f32.f16.f16.f32 "
                        "{%0,%1,%2,%3}, {%4,%5,%6,%7}, {%8,%9}, {%0,%1,%2,%3};"
                        : "+f"(acc[mf][nf][0]), "+f"(acc[mf][nf][1]),
                          "+f"(acc[mf][nf][2]), "+f"(acc[mf][nf][3])
                        : "r"(afr[mf][0]), "r"(afr[mf][1]),
                          "r"(afr[mf][2]), "r"(afr[mf][3]),
                          "r"(bfr[nf][0]), "r"(bfr[nf][1]));
                }
            }
        }
    }

    // Store C. c0/c1 at (gid, tig*2/+1); c2/c3 at (gid+8, same cols).
#pragma unroll
    for (int mf = 0; mf < 4; mf++) {
#pragma unroll
        for (int nf = 0; nf < 4; nf++) {
            int row0 = ti + wm * 64 + mf * 16 + gid;
            int col  = td + wn * 32 + nf * 8 + tig * 2;
            float* o0 = out + (size_t)row0 * (BB * DD) + (size_t)b * DD + col;
            float* o1 = out + (size_t)(row0 + 8) * (BB * DD) + (size_t)b * DD + col;
            o0[0] = acc[mf][nf][0];
            o0[1] = acc[mf][nf][1];
            o1[0] = acc[mf][nf][2];
            o1[1] = acc[mf][nf][3];
        }
    }
}

// ---------------------------------------------------------------------------
// Launch. Inputs: 0:x 1:layer_input(unused) 2:pe 3:encoder_mask 4:W 5:b
// ---------------------------------------------------------------------------
extern "C" void kernel_launch(void* const* d_in, const int* in_sizes, int n_in,
                              void* d_out, int out_size) {
    const float* x    = (const float*)d_in[0];
    const float* pe   = (const float*)d_in[2];
    const void*  mask = d_in[3];
    const float* W    = (const float*)d_in[4];
    const float* bias = (const float*)d_in[5];
    float*       out  = (float*)d_out;

    sniff_kernel<<<1, 256>>>((const int*)mask);
    mask_kernel<<<BB, 1024>>>(mask);
    pred_kernel<<<(SS * BB) / 8, 256>>>(x, W, bias);

    dim3 pgrid(SS, BB);
    prob_kernel<<<pgrid, 256>>>();

    dim3 tgrid(SS / 64, DD / 64, BB);
    transpose_kernel<<<tgrid, 256>>>(pe);

    dim3 ggrid(DD / 128, SS / 128, BB);
    gemm_fp16_kernel<<<ggrid, 256>>>(out);
}

// round 8
// speedup vs baseline: 1.3475x; 1.3475x over previous
#include <cuda_runtime.h>
#include <cuda_bf16.h>
#include <cuda_fp16.h>
#include <math.h>
#include <stdint.h>

// Problem constants
#define SS 1024   // sequence length S
#define BB 32     // batch B
#define DD 1024   // model dim D

// GEMM tiling
#define MT 128
#define NT 256
#define BK 64
#define NKT (SS / BK)                 // 16 K-chunks
#define AST 72                        // smem row stride (halves): 144B, LDSM conflict-free
#define A_HALVES (128 * AST)
#define B_HALVES (256 * AST)
#define BUF_HALVES (A_HALVES + B_HALVES)
#define GEMM_SMEM (2 * BUF_HALVES * 2)   // bytes, double-buffered

// Scratch (device globals — allocation-guard-safe)
__device__ __half g_probH[(size_t)BB * SS * SS];   // (B, S, S) fp16
__device__ __half g_peT[(size_t)BB * DD * SS];     // (B, D, S) fp16
__device__ float g_pred[SS * BB];
__device__ float g_valid[BB * SS];
__device__ float g_slen[BB];
__device__ float g_lang[BB];
__device__ int   g_mask_is_i32;

__device__ __forceinline__ uint32_t smem_u32(const void* p) {
    uint32_t a;
    asm("{ .reg .u64 t; cvta.to.shared.u64 t, %1; cvt.u32.u64 %0, t; }"
        : "=r"(a) : "l"(p));
    return a;
}
#define CP_ASYNC16(dst, src) \
    asm volatile("cp.async.cg.shared.global [%0], [%1], 16;" :: "r"(dst), "l"(src))
#define CP_COMMIT() asm volatile("cp.async.commit_group;" ::: "memory")
#define CP_WAIT(n)  asm volatile("cp.async.wait_group %0;" :: "n"(n) : "memory")
#define LDSM4(r0, r1, r2, r3, a) \
    asm volatile("ldmatrix.sync.aligned.m8n8.x4.shared.b16 {%0,%1,%2,%3}, [%4];" \
                 : "=r"(r0), "=r"(r1), "=r"(r2), "=r"(r3) : "r"(a))

// ---------------------------------------------------------------------------
// K-1: sniff the mask dtype (bool delivered as uint8 or int32).
// ---------------------------------------------------------------------------
__global__ void sniff_kernel(const int* __restrict__ m) {
    __shared__ int bad[256];
    int tid = threadIdx.x;
    int any = 0;
#pragma unroll
    for (int t = 0; t < 32; t++) {
        int v = m[t * 256 + tid];
        any |= ((unsigned)v > 1u) ? 1 : 0;
    }
    bad[tid] = any;
    __syncthreads();
    if (tid == 0) {
        int a = 0;
        for (int k = 0; k < 256; k++) a |= bad[k];
        g_mask_is_i32 = a ? 0 : 1;
    }
}

// ---------------------------------------------------------------------------
// K0: expand mask + per-batch reduction.
// ---------------------------------------------------------------------------
__global__ __launch_bounds__(1024) void mask_kernel(const void* __restrict__ maskp) {
    int b = blockIdx.x;
    int j = threadIdx.x;

    int mv;
    if (g_mask_is_i32) mv = ((const int*)maskp)[b * SS + j];
    else               mv = ((const unsigned char*)maskp)[b * SS + j];

    float valid = (mv == 0) ? 1.0f : 0.0f;
    g_valid[b * SS + j] = valid;

    __shared__ float red[32];
    float c = valid;
#pragma unroll
    for (int o = 16; o; o >>= 1) c += __shfl_xor_sync(0xFFFFFFFFu, c, o);
    if ((j & 31) == 0) red[j >> 5] = c;
    __syncthreads();
    if (j == 0) {
        float s = 0.0f;
#pragma unroll
        for (int w = 0; w < 32; w++) s += red[w];
        g_slen[b] = s;
        g_lang[b] = (float)SS - s;
    }
}

// ---------------------------------------------------------------------------
// K1: pred[i,b] = sigmoid(x[i,b,:]·W + bias) * slen[b].  One warp per (i,b).
// ---------------------------------------------------------------------------
__global__ __launch_bounds__(256) void pred_kernel(
    const float* __restrict__ x, const float* __restrict__ W,
    const float* __restrict__ bias)
{
    int warp = (blockIdx.x * blockDim.x + threadIdx.x) >> 5;
    int lane = threadIdx.x & 31;
    int i = warp >> 5;
    int b = warp & 31;

    const float4* xv = (const float4*)(x + ((size_t)i * BB + b) * DD);
    const float4* wv = (const float4*)W;
    float sum = 0.0f;
#pragma unroll
    for (int t = 0; t < 8; t++) {
        float4 a = xv[t * 32 + lane];
        float4 w = wv[t * 32 + lane];
        sum += a.x * w.x + a.y * w.y + a.z * w.z + a.w * w.w;
    }
#pragma unroll
    for (int o = 16; o; o >>= 1) sum += __shfl_xor_sync(0xFFFFFFFFu, sum, o);
    if (lane == 0) {
        float t = sum + bias[0];
        float p = 1.0f / (1.0f + expf(-t));
        g_pred[i * BB + b] = p * g_slen[b];
    }
}

// ---------------------------------------------------------------------------
// K2: normalized, gated prob row -> fp16, stored (B, S, S).
// Fast reciprocal (MUFU.RCP) instead of IEEE division; vectorized I/O.
// ---------------------------------------------------------------------------
__global__ __launch_bounds__(256) void prob_kernel() {
    int i = blockIdx.x;
    int b = blockIdx.y;
    int tid = threadIdx.x;

    float c = g_pred[i * BB + b] + g_lang[b];   // d = c - j
    const float* vrow = g_valid + b * SS;

    float4 vv = *(const float4*)(vrow + 4 * tid);
    float v[4];
    float lsum = 0.0f;
#pragma unroll
    for (int t = 0; t < 4; t++) {
        float j = (float)(4 * tid + t);
        float d = c - j;
        float vk = (t == 0) ? vv.x : (t == 1) ? vv.y : (t == 2) ? vv.z : vv.w;
        float val = __fdividef(vk, d * d + 0.001f);
        v[t] = val;
        lsum += val;
    }

    __shared__ float red[8];
#pragma unroll
    for (int o = 16; o; o >>= 1) lsum += __shfl_xor_sync(0xFFFFFFFFu, lsum, o);
    if ((tid & 31) == 0) red[tid >> 5] = lsum;
    __syncthreads();
    if (tid == 0) {
        float s = 0.0f;
#pragma unroll
        for (int w = 0; w < 8; w++) s += red[w];
        red[0] = (s > 0.0f) ? (vrow[i] / s) : 0.0f;
    }
    __syncthreads();
    float scale = red[0];

    __half h[4];
#pragma unroll
    for (int t = 0; t < 4; t++) h[t] = __float2half_rn(v[t] * scale);
    *(uint2*)(g_probH + ((size_t)b * SS + i) * SS + 4 * tid) = *(uint2*)h;
}

// ---------------------------------------------------------------------------
// K2b: transpose pe (S,B,D) -> peT (B,D,S) fp16. 64x64 tile per block.
// ---------------------------------------------------------------------------
__global__ __launch_bounds__(256) void transpose_kernel(const float* __restrict__ pe) {
    __shared__ float t[64][65];
    int j0 = blockIdx.x * 64;
    int d0 = blockIdx.y * 64;
    int b  = blockIdx.z;
    int tid = threadIdx.x;

#pragma unroll
    for (int q = 0; q < 4; q++) {
        int idx = tid + 256 * q;
        int jr  = idx >> 4;
        int c4  = idx & 15;
        float4 v = *(const float4*)(pe + ((size_t)(j0 + jr) * BB + b) * DD + d0 + c4 * 4);
        t[jr][c4 * 4 + 0] = v.x;
        t[jr][c4 * 4 + 1] = v.y;
        t[jr][c4 * 4 + 2] = v.z;
        t[jr][c4 * 4 + 3] = v.w;
    }
    __syncthreads();

#pragma unroll
    for (int q = 0; q < 4; q++) {
        int idx = tid + 256 * q;
        int dr  = idx >> 4;
        int c4  = idx & 15;
        __half h[4];
#pragma unroll
        for (int k = 0; k < 4; k++) h[k] = __float2half_rn(t[c4 * 4 + k][dr]);
        size_t dst = ((size_t)b * DD + d0 + dr) * SS + j0 + c4 * 4;
        *(uint2*)&g_peT[dst] = *(uint2*)h;
    }
}

// ---------------------------------------------------------------------------
// K3: batched GEMM, fp16 mma.sync m16n8k16 (fp32 accum).
// Block tile 128(M) x 256(N), BK=64, double-buffered cp.async smem pipeline.
// 8 warps (2m x 4n), warp tile 64x64. Fragments via ldmatrix.x4 (both K-major).
// ---------------------------------------------------------------------------
__global__ __launch_bounds__(256, 1) void gemm_fp16_kernel(float* __restrict__ out) {
    extern __shared__ __half sm[];
    const uint32_t sbase = smem_u32(sm);

    const int b  = blockIdx.z;
    const int ti = blockIdx.y * MT;
    const int td = blockIdx.x * NT;

    const int tid  = threadIdx.x;
    const int lane = tid & 31;
    const int warp = tid >> 5;
    const int wm   = warp & 1;
    const int wn   = warp >> 1;
    const int gid  = lane >> 2;
    const int tig  = lane & 3;

    // ldmatrix per-lane offsets (halves)
    const int lrow = lane & 7;
    const int lq   = lane >> 3;
    const int a_off = (lrow + 8 * (lq & 1)) * AST + 8 * (lq >> 1);
    const int b_off = (lrow + 8 * (lq >> 1)) * AST + 8 * (lq & 1);

    // cp.async mappings: A 128 rows x 8 chunks (16B), B 256 rows x 8 chunks
    const int arow = tid >> 1;            // pairs: t adds 128 rows? (see loop)
    const __half* pA = g_probH + ((size_t)b * SS + ti) * SS;
    const __half* pB = g_peT   + ((size_t)b * DD + td) * SS;

    float acc[4][8][4];
#pragma unroll
    for (int mf = 0; mf < 4; mf++)
#pragma unroll
        for (int nf = 0; nf < 8; nf++)
#pragma unroll
            for (int r = 0; r < 4; r++) acc[mf][nf][r] = 0.0f;

    // ---- pipeline: load stage kt into buffer kt&1 ----
    auto load_stage = [&](int kt) {
        const int j0 = kt * BK;
        const uint32_t base = sbase + (uint32_t)((kt & 1) * BUF_HALVES) * 2;
#pragma unroll
        for (int t = 0; t < 4; t++) {                 // A: 1024 chunks / 256 thr
            int idx = tid + 256 * t;
            int row = idx >> 3, c = idx & 7;
            CP_ASYNC16(base + (uint32_t)(row * AST + c * 8) * 2,
                       pA + (size_t)row * SS + j0 + c * 8);
        }
#pragma unroll
        for (int t = 0; t < 8; t++) {                 // B: 2048 chunks / 256 thr
            int idx = tid + 256 * t;
            int row = idx >> 3, c = idx & 7;
            CP_ASYNC16(base + (uint32_t)(A_HALVES + row * AST + c * 8) * 2,
                       pB + (size_t)row * SS + j0 + c * 8);
        }
        CP_COMMIT();
    };

    load_stage(0);

    for (int kt = 0; kt < NKT; kt++) {
        if (kt + 1 < NKT) {
            load_stage(kt + 1);
            CP_WAIT(1);
        } else {
            CP_WAIT(0);
        }
        __syncthreads();

        const uint32_t abase = sbase + (uint32_t)((kt & 1) * BUF_HALVES) * 2;
        const uint32_t bbase = abase + (uint32_t)A_HALVES * 2;

#pragma unroll
        for (int ks = 0; ks < BK; ks += 16) {
            uint32_t afr[4][4];
#pragma unroll
            for (int mf = 0; mf < 4; mf++) {
                uint32_t ad = abase + (uint32_t)(((wm * 64 + mf * 16) * AST + ks) + a_off) * 2;
                LDSM4(afr[mf][0], afr[mf][1], afr[mf][2], afr[mf][3], ad);
            }
            uint32_t bfr[8][2];
#pragma unroll
            for (int np = 0; np < 4; np++) {
                uint32_t bd = bbase + (uint32_t)(((wn * 64 + np * 16) * AST + ks) + b_off) * 2;
                LDSM4(bfr[2 * np][0], bfr[2 * np][1],
                      bfr[2 * np + 1][0], bfr[2 * np + 1][1], bd);
            }
#pragma unroll
            for (int mf = 0; mf < 4; mf++) {
#pragma unroll
                for (int nf = 0; nf < 8; nf++) {
                    asm volatile(
                        "mma.sync.aligned.m16n8k16.row.col.f32.f16.f16.f32 "
                        "{%0,%1,%2,%3}, {%4,%5,%6,%7}, {%8,%9}, {%0,%1,%2,%3};"
                        : "+f"(acc[mf][nf][0]), "+f"(acc[mf][nf][1]),
                          "+f"(acc[mf][nf][2]), "+f"(acc[mf][nf][3])
                        : "r"(afr[mf][0]), "r"(afr[mf][1]),
                          "r"(afr[mf][2]), "r"(afr[mf][3]),
                          "r"(bfr[nf][0]), "r"(bfr[nf][1]));
                }
            }
        }
        __syncthreads();
    }

    // Epilogue: fragment c0/c1 at (gid, tig*2/+1), c2/c3 at (gid+8, same cols)
#pragma unroll
    for (int mf = 0; mf < 4; mf++) {
#pragma unroll
        for (int nf = 0; nf < 8; nf++) {
            int row0 = ti + wm * 64 + mf * 16 + gid;
            int col  = td + wn * 64 + nf * 8 + tig * 2;
            float* o0 = out + (size_t)row0 * (BB * DD) + (size_t)b * DD + col;
            float* o1 = out + (size_t)(row0 + 8) * (BB * DD) + (size_t)b * DD + col;
            *(float2*)o0 = make_float2(acc[mf][nf][0], acc[mf][nf][1]);
            *(float2*)o1 = make_float2(acc[mf][nf][2], acc[mf][nf][3]);
        }
    }
    (void)arow;
}

// ---------------------------------------------------------------------------
// Launch. Inputs: 0:x 1:layer_input(unused) 2:pe 3:encoder_mask 4:W 5:b
// ---------------------------------------------------------------------------
extern "C" void kernel_launch(void* const* d_in, const int* in_sizes, int n_in,
                              void* d_out, int out_size) {
    const float* x    = (const float*)d_in[0];
    const float* pe   = (const float*)d_in[2];
    const void*  mask = d_in[3];
    const float* W    = (const float*)d_in[4];
    const float* bias = (const float*)d_in[5];
    float*       out  = (float*)d_out;

    cudaFuncSetAttribute(gemm_fp16_kernel,
                         cudaFuncAttributeMaxDynamicSharedMemorySize, GEMM_SMEM);

    sniff_kernel<<<1, 256>>>((const int*)mask);
    mask_kernel<<<BB, 1024>>>(mask);
    pred_kernel<<<(SS * BB) / 8, 256>>>(x, W, bias);

    dim3 pgrid(SS, BB);
    prob_kernel<<<pgrid, 256>>>();

    dim3 tgrid(SS / 64, DD / 64, BB);
    transpose_kernel<<<tgrid, 256>>>(pe);

    dim3 ggrid(DD / NT, SS / MT, BB);
    gemm_fp16_kernel<<<ggrid, 256, GEMM_SMEM>>>(out);
}

// round 9
// speedup vs baseline: 2.5033x; 1.8577x over previous
#include <cuda_runtime.h>
#include <cuda_bf16.h>
#include <cuda_fp16.h>
#include <math.h>
#include <stdint.h>

// Problem constants
#define SS 1024   // sequence length S
#define BB 32     // batch B
#define DD 1024   // model dim D

// GEMM tiling
#define MT 128
#define NT 256
#define BK 64
#define AST 72                        // smem row stride (halves)
#define A_HALVES (128 * AST)
#define B_HALVES (256 * AST)
#define BUF_HALVES (A_HALVES + B_HALVES)
#define GEMM_SMEM (2 * BUF_HALVES * 2)   // bytes, double-buffered

// Scratch (device globals — allocation-guard-safe)
__device__ __half g_probH[(size_t)BB * SS * SS];   // (B, r, c) compacted prob, fp16
__device__ __half g_peT[(size_t)BB * DD * SS];     // (B, d, c) compacted gathered pe, fp16
__device__ float g_pred[SS * BB];
__device__ float g_valid[BB * SS];
__device__ int   g_idx[BB * SS];                   // per-batch compacted valid positions
__device__ int   g_nv[BB];                         // per-batch valid count
__device__ float g_slen[BB];
__device__ float g_lang[BB];
__device__ int   g_mask_is_i32;

__device__ __forceinline__ uint32_t smem_u32(const void* p) {
    uint32_t a;
    asm("{ .reg .u64 t; cvta.to.shared.u64 t, %1; cvt.u32.u64 %0, t; }"
        : "=r"(a) : "l"(p));
    return a;
}
#define CP_ASYNC16(dst, src) \
    asm volatile("cp.async.cg.shared.global [%0], [%1], 16;" :: "r"(dst), "l"(src))
#define CP_COMMIT() asm volatile("cp.async.commit_group;" ::: "memory")
#define CP_WAIT(n)  asm volatile("cp.async.wait_group %0;" :: "n"(n) : "memory")
#define LDSM4(r0, r1, r2, r3, a) \
    asm volatile("ldmatrix.sync.aligned.m8n8.x4.shared.b16 {%0,%1,%2,%3}, [%4];" \
                 : "=r"(r0), "=r"(r1), "=r"(r2), "=r"(r3) : "r"(a))

// ---------------------------------------------------------------------------
// K-1: sniff the mask dtype (bool delivered as uint8 or int32).
// ---------------------------------------------------------------------------
__global__ void sniff_kernel(const int* __restrict__ m) {
    __shared__ int bad[256];
    int tid = threadIdx.x;
    int any = 0;
#pragma unroll
    for (int t = 0; t < 32; t++) {
        int v = m[t * 256 + tid];
        any |= ((unsigned)v > 1u) ? 1 : 0;
    }
    bad[tid] = any;
    __syncthreads();
    if (tid == 0) {
        int a = 0;
        for (int k = 0; k < 256; k++) a |= bad[k];
        g_mask_is_i32 = a ? 0 : 1;
    }
}

// ---------------------------------------------------------------------------
// K0: expand mask + per-batch reduction + compaction scan.
// One block (1024 thr) per batch. idx[b][r] = r-th valid position.
// ---------------------------------------------------------------------------
__global__ __launch_bounds__(1024) void mask_kernel(const void* __restrict__ maskp) {
    int b = blockIdx.x;
    int j = threadIdx.x;
    int lane = j & 31;
    int w    = j >> 5;

    int mv;
    if (g_mask_is_i32) mv = ((const int*)maskp)[b * SS + j];
    else               mv = ((const unsigned char*)maskp)[b * SS + j];
    int valid = (mv == 0) ? 1 : 0;
    g_valid[b * SS + j] = (float)valid;

    unsigned ball = __ballot_sync(0xFFFFFFFFu, valid);
    int rank = __popc(ball & ((1u << lane) - 1));   // exclusive rank in warp
    int wcnt = __popc(ball);

    __shared__ int wsum[32];
    if (lane == 0) wsum[w] = wcnt;
    __syncthreads();
    if (j < 32) {
        int v = wsum[j];
#pragma unroll
        for (int o = 1; o < 32; o <<= 1) {
            int t = __shfl_up_sync(0xFFFFFFFFu, v, o);
            if (lane >= o) v += t;
        }
        wsum[j] = v;    // inclusive scan of warp counts
    }
    __syncthreads();
    int base = (w == 0) ? 0 : wsum[w - 1];
    if (valid) g_idx[b * SS + base + rank] = j;

    if (j == 0) {
        int tot = wsum[31];
        g_nv[b]   = tot;
        g_slen[b] = (float)tot;
        g_lang[b] = (float)(SS - tot);
    }
}

// ---------------------------------------------------------------------------
// K0b: zero-fill invalid output rows (d_out is poisoned by harness).
// Grid (S, B), 256 threads; each writes 4 floats.
// ---------------------------------------------------------------------------
__global__ __launch_bounds__(256) void zerofill_kernel(float* __restrict__ out) {
    int i = blockIdx.x;
    int b = blockIdx.y;
    if (g_valid[b * SS + i] != 0.0f) return;
    float4 z = make_float4(0.f, 0.f, 0.f, 0.f);
    *(float4*)(out + (size_t)i * (BB * DD) + (size_t)b * DD + 4 * threadIdx.x) = z;
}

// ---------------------------------------------------------------------------
// K1: pred[i,b] = sigmoid(x[i,b,:]·W + bias) * slen[b].  One warp per (i,b).
// Skips invalid (i,b) rows (their outputs are never used).
// ---------------------------------------------------------------------------
__global__ __launch_bounds__(256) void pred_kernel(
    const float* __restrict__ x, const float* __restrict__ W,
    const float* __restrict__ bias)
{
    int warp = (blockIdx.x * blockDim.x + threadIdx.x) >> 5;
    int lane = threadIdx.x & 31;
    int i = warp >> 5;
    int b = warp & 31;
    if (g_valid[b * SS + i] == 0.0f) return;

    const float4* xv = (const float4*)(x + ((size_t)i * BB + b) * DD);
    const float4* wv = (const float4*)W;
    float sum = 0.0f;
#pragma unroll
    for (int t = 0; t < 8; t++) {
        float4 a = xv[t * 32 + lane];
        float4 w = wv[t * 32 + lane];
        sum += a.x * w.x + a.y * w.y + a.z * w.z + a.w * w.w;
    }
#pragma unroll
    for (int o = 16; o; o >>= 1) sum += __shfl_xor_sync(0xFFFFFFFFu, sum, o);
    if (lane == 0) {
        float t = sum + bias[0];
        float p = 1.0f / (1.0f + expf(-t));
        g_pred[i * BB + b] = p * g_slen[b];
    }
}

// ---------------------------------------------------------------------------
// K2: compacted prob row.  Block (r, b): r-th valid output row of batch b.
// Ac[b][r][c] = normalized 1/(d^2+eps) over compacted valid columns c.
// Columns c >= nv written as zero (pads the GEMM K range).
// ---------------------------------------------------------------------------
__global__ __launch_bounds__(256) void prob_kernel() {
    int r = blockIdx.x;
    int b = blockIdx.y;
    int nv = g_nv[b];
    if (r >= nv) return;
    int tid = threadIdx.x;

    int i = g_idx[b * SS + r];
    float c0 = g_pred[i * BB + b] + g_lang[b];   // d = c0 - j

    const int* idxp = g_idx + b * SS;
    float v[4];
    float lsum = 0.0f;
#pragma unroll
    for (int t = 0; t < 4; t++) {
        int cpos = 4 * tid + t;
        float val = 0.0f;
        if (cpos < nv) {
            float j = (float)idxp[cpos];
            float d = c0 - j;
            val = __fdividef(1.0f, d * d + 0.001f);
        }
        v[t] = val;
        lsum += val;
    }

    __shared__ float red[8];
#pragma unroll
    for (int o = 16; o; o >>= 1) lsum += __shfl_xor_sync(0xFFFFFFFFu, lsum, o);
    if ((tid & 31) == 0) red[tid >> 5] = lsum;
    __syncthreads();
    if (tid == 0) {
        float s = 0.0f;
#pragma unroll
        for (int w = 0; w < 8; w++) s += red[w];
        red[0] = __fdividef(1.0f, s);   // row gate = 1 (r is valid by construction)
    }
    __syncthreads();
    float scale = red[0];

    __half h[4];
#pragma unroll
    for (int t = 0; t < 4; t++) h[t] = __float2half_rn(v[t] * scale);
    *(uint2*)(g_probH + ((size_t)b * SS + r) * SS + 4 * tid) = *(uint2*)h;
}

// ---------------------------------------------------------------------------
// K2b: gather+transpose pe: peTc[b][d][c] = pe[idx[b][c], b, d] (fp16).
// 64(c) x 64(d) tile per block. Blocks beyond ceil64(nv) exit; pad cols -> 0.
// ---------------------------------------------------------------------------
__global__ __launch_bounds__(256) void gather_kernel(const float* __restrict__ pe) {
    int c0 = blockIdx.x * 64;
    int d0 = blockIdx.y * 64;
    int b  = blockIdx.z;
    int nv = g_nv[b];
    int kceil = ((nv + BK - 1) / BK) * BK;
    if (c0 >= kceil) return;
    int tid = threadIdx.x;

    __shared__ float t[64][65];

#pragma unroll
    for (int q = 0; q < 4; q++) {
        int idx = tid + 256 * q;
        int cc  = idx >> 4;               // 0..63 (c within tile)
        int c4  = idx & 15;               // float4 within d-row
        int c   = c0 + cc;
        float4 v = make_float4(0.f, 0.f, 0.f, 0.f);
        if (c < nv) {
            int j = g_idx[b * SS + c];
            v = *(const float4*)(pe + ((size_t)j * BB + b) * DD + d0 + c4 * 4);
        }
        t[cc][c4 * 4 + 0] = v.x;
        t[cc][c4 * 4 + 1] = v.y;
        t[cc][c4 * 4 + 2] = v.z;
        t[cc][c4 * 4 + 3] = v.w;
    }
    __syncthreads();

#pragma unroll
    for (int q = 0; q < 4; q++) {
        int idx = tid + 256 * q;
        int dr  = idx >> 4;               // 0..63 (d within tile)
        int c4  = idx & 15;               // 4 c's
        __half h[4];
#pragma unroll
        for (int k = 0; k < 4; k++) h[k] = __float2half_rn(t[c4 * 4 + k][dr]);
        size_t dst = ((size_t)b * DD + d0 + dr) * SS + c0 + c4 * 4;
        *(uint2*)&g_peT[dst] = *(uint2*)h;
    }
}

// ---------------------------------------------------------------------------
// K3: compacted batched GEMM, fp16 mma.sync m16n8k16 (fp32 accum).
// Oc[r,d] = sum_c Ac[b,r,c] * peTc[b,d,c]; scatter rows r -> idx[b][r].
// Block tile 128x256, dynamic K = ceil(nv/64), double-buffered cp.async.
// ---------------------------------------------------------------------------
__global__ __launch_bounds__(256, 1) void gemm_fp16_kernel(float* __restrict__ out) {
    const int b  = blockIdx.z;
    const int ti = blockIdx.y * MT;
    const int td = blockIdx.x * NT;

    const int nI = g_nv[b];
    if (ti >= nI) return;                      // whole tile is dead rows
    const int kc = (nI + BK - 1) / BK;         // K chunks (nJ == nI)

    extern __shared__ __half sm[];
    const uint32_t sbase = smem_u32(sm);

    const int tid  = threadIdx.x;
    const int lane = tid & 31;
    const int warp = tid >> 5;
    const int wm   = warp & 1;
    const int wn   = warp >> 1;
    const int gid  = lane >> 2;
    const int tig  = lane & 3;

    const int lrow = lane & 7;
    const int lq   = lane >> 3;
    const int a_off = (lrow + 8 * (lq & 1)) * AST + 8 * (lq >> 1);
    const int b_off = (lrow + 8 * (lq >> 1)) * AST + 8 * (lq & 1);

    const __half* pA = g_probH + ((size_t)b * SS + ti) * SS;
    const __half* pB = g_peT   + ((size_t)b * DD + td) * SS;

    float acc[4][8][4];
#pragma unroll
    for (int mf = 0; mf < 4; mf++)
#pragma unroll
        for (int nf = 0; nf < 8; nf++)
#pragma unroll
            for (int r = 0; r < 4; r++) acc[mf][nf][r] = 0.0f;

    auto load_stage = [&](int kt) {
        const int j0 = kt * BK;
        const uint32_t base = sbase + (uint32_t)((kt & 1) * BUF_HALVES) * 2;
#pragma unroll
        for (int t = 0; t < 4; t++) {
            int idx = tid + 256 * t;
            int row = idx >> 3, c = idx & 7;
            CP_ASYNC16(base + (uint32_t)(row * AST + c * 8) * 2,
                       pA + (size_t)row * SS + j0 + c * 8);
        }
#pragma unroll
        for (int t = 0; t < 8; t++) {
            int idx = tid + 256 * t;
            int row = idx >> 3, c = idx & 7;
            CP_ASYNC16(base + (uint32_t)(A_HALVES + row * AST + c * 8) * 2,
                       pB + (size_t)row * SS + j0 + c * 8);
        }
        CP_COMMIT();
    };

    load_stage(0);

    for (int kt = 0; kt < kc; kt++) {
        if (kt + 1 < kc) {
            load_stage(kt + 1);
            CP_WAIT(1);
        } else {
            CP_WAIT(0);
        }
        __syncthreads();

        const uint32_t abase = sbase + (uint32_t)((kt & 1) * BUF_HALVES) * 2;
        const uint32_t bbase = abase + (uint32_t)A_HALVES * 2;

#pragma unroll
        for (int ks = 0; ks < BK; ks += 16) {
            uint32_t afr[4][4];
#pragma unroll
            for (int mf = 0; mf < 4; mf++) {
                uint32_t ad = abase + (uint32_t)(((wm * 64 + mf * 16) * AST + ks) + a_off) * 2;
                LDSM4(afr[mf][0], afr[mf][1], afr[mf][2], afr[mf][3], ad);
            }
            uint32_t bfr[8][2];
#pragma unroll
            for (int np = 0; np < 4; np++) {
                uint32_t bd = bbase + (uint32_t)(((wn * 64 + np * 16) * AST + ks) + b_off) * 2;
                LDSM4(bfr[2 * np][0], bfr[2 * np][1],
                      bfr[2 * np + 1][0], bfr[2 * np + 1][1], bd);
            }
#pragma unroll
            for (int mf = 0; mf < 4; mf++) {
#pragma unroll
                for (int nf = 0; nf < 8; nf++) {
                    asm volatile(
                        "mma.sync.aligned.m16n8k16.row.col.f32.f16.f16.f32 "
                        "{%0,%1,%2,%3}, {%4,%5,%6,%7}, {%8,%9}, {%0,%1,%2,%3};"
                        : "+f"(acc[mf][nf][0]), "+f"(acc[mf][nf][1]),
                          "+f"(acc[mf][nf][2]), "+f"(acc[mf][nf][3])
                        : "r"(afr[mf][0]), "r"(afr[mf][1]),
                          "r"(afr[mf][2]), "r"(afr[mf][3]),
                        "r"(bfr[nf][0]), "r"(bfr[nf][1]));
                }
            }
        }
        __syncthreads();
    }

    // Epilogue: scatter valid rows through idx.
    const int* idxp = g_idx + b * SS;
#pragma unroll
    for (int mf = 0; mf < 4; mf++) {
        int r0 = ti + wm * 64 + mf * 16 + gid;
        int r1 = r0 + 8;
        int ig0 = (r0 < nI) ? idxp[r0] : -1;
        int ig1 = (r1 < nI) ? idxp[r1] : -1;
#pragma unroll
        for (int nf = 0; nf < 8; nf++) {
            int col = td + wn * 64 + nf * 8 + tig * 2;
            if (ig0 >= 0)
                *(float2*)(out + (size_t)ig0 * (BB * DD) + (size_t)b * DD + col) =
                    make_float2(acc[mf][nf][0], acc[mf][nf][1]);
            if (ig1 >= 0)
                *(float2*)(out + (size_t)ig1 * (BB * DD) + (size_t)b * DD + col) =
                    make_float2(acc[mf][nf][2], acc[mf][nf][3]);
        }
    }
}

// ---------------------------------------------------------------------------
// Launch. Inputs: 0:x 1:layer_input(unused) 2:pe 3:encoder_mask 4:W 5:b
// ---------------------------------------------------------------------------
extern "C" void kernel_launch(void* const* d_in, const int* in_sizes, int n_in,
                              void* d_out, int out_size) {
    const float* x    = (const float*)d_in[0];
    const float* pe   = (const float*)d_in[2];
    const void*  mask = d_in[3];
    const float* W    = (const float*)d_in[4];
    const float* bias = (const float*)d_in[5];
    float*       out  = (float*)d_out;

    cudaFuncSetAttribute(gemm_fp16_kernel,
                         cudaFuncAttributeMaxDynamicSharedMemorySize, GEMM_SMEM);

    sniff_kernel<<<1, 256>>>((const int*)mask);
    mask_kernel<<<BB, 1024>>>(mask);

    dim3 zgrid(SS, BB);
    zerofill_kernel<<<zgrid, 256>>>(out);

    pred_kernel<<<(SS * BB) / 8, 256>>>(x, W, bias);

    dim3 pgrid(SS, BB);
    prob_kernel<<<pgrid, 256>>>();

    dim3 ggrid2(SS / 64, DD / 64, BB);
    gather_kernel<<<ggrid2, 256>>>(pe);

    dim3 ggrid(DD / NT, SS / MT, BB);
    gemm_fp16_kernel<<<ggrid, 256, GEMM_SMEM>>>(out);
}

// round 10
// speedup vs baseline: 2.7287x; 1.0900x over previous
#include <cuda_runtime.h>
#include <cuda_bf16.h>
#include <cuda_fp16.h>
#include <math.h>
#include <stdint.h>

// Problem constants
#define SS 1024   // sequence length S
#define BB 32     // batch B
#define DD 1024   // model dim D

// GEMM tiling
#define MT 128
#define NT 256
#define BK 64
#define AST 72                        // smem row stride (halves)
#define A_HALVES (128 * AST)
#define B_HALVES (256 * AST)
#define BUF_HALVES (A_HALVES + B_HALVES)
#define GEMM_SMEM (2 * BUF_HALVES * 2)   // bytes, double-buffered

// Scratch (device globals — allocation-guard-safe)
__device__ __half g_probH[(size_t)BB * SS * SS];   // (B, r, c) compacted prob, fp16
__device__ __half g_peT[(size_t)BB * DD * SS];     // (B, d, c) compacted gathered pe, fp16
__device__ float g_valid[BB * SS];
__device__ int   g_idx[BB * SS];                   // per-batch compacted valid positions
__device__ int   g_nv[BB];                         // per-batch valid count

__device__ __forceinline__ uint32_t smem_u32(const void* p) {
    uint32_t a;
    asm("{ .reg .u64 t; cvta.to.shared.u64 t, %1; cvt.u32.u64 %0, t; }"
        : "=r"(a) : "l"(p));
    return a;
}
#define CP_ASYNC16(dst, src) \
    asm volatile("cp.async.cg.shared.global [%0], [%1], 16;" :: "r"(dst), "l"(src))
#define CP_COMMIT() asm volatile("cp.async.commit_group;" ::: "memory")
#define CP_WAIT(n)  asm volatile("cp.async.wait_group %0;" :: "n"(n) : "memory")
#define LDSM4(r0, r1, r2, r3, a) \
    asm volatile("ldmatrix.sync.aligned.m8n8.x4.shared.b16 {%0,%1,%2,%3}, [%4];" \
                 : "=r"(r0), "=r"(r1), "=r"(r2), "=r"(r3) : "r"(a))

// ---------------------------------------------------------------------------
// K0: mask kernel with inline dtype sniff + compaction scan.
// One block (1024 thr) per batch. idx[b][r] = r-th valid position.
// Sniff: scan the first 8192 int32 words (= uint8 buffer size). If any word
// > 1, the mask is packed uint8 bools; else int32. L2-hot, ~free per block.
// ---------------------------------------------------------------------------
__global__ __launch_bounds__(1024) void mask_kernel(const void* __restrict__ maskp) {
    int b = blockIdx.x;
    int j = threadIdx.x;
    int lane = j & 31;
    int w    = j >> 5;

    const int* m32 = (const int*)maskp;
    int any = 0;
#pragma unroll
    for (int t = 0; t < 8; t++) {
        any |= ((unsigned)m32[t * 1024 + j] > 1u) ? 1 : 0;
    }
    int is_u8 = __syncthreads_or(any);

    int mv;
    if (is_u8) mv = ((const unsigned char*)maskp)[b * SS + j];
    else       mv = m32[b * SS + j];
    int valid = (mv == 0) ? 1 : 0;
    g_valid[b * SS + j] = (float)valid;

    unsigned ball = __ballot_sync(0xFFFFFFFFu, valid);
    int rank = __popc(ball & ((1u << lane) - 1));
    int wcnt = __popc(ball);

    __shared__ int wsum[32];
    if (lane == 0) wsum[w] = wcnt;
    __syncthreads();
    if (j < 32) {
        int v = wsum[j];
#pragma unroll
        for (int o = 1; o < 32; o <<= 1) {
            int t = __shfl_up_sync(0xFFFFFFFFu, v, o);
            if (lane >= o) v += t;
        }
        wsum[j] = v;
    }
    __syncthreads();
    int base = (w == 0) ? 0 : wsum[w - 1];
    if (valid) g_idx[b * SS + base + rank] = j;

    if (j == 0) g_nv[b] = wsum[31];
}

// ---------------------------------------------------------------------------
// K0b: zero-fill invalid output rows (d_out is poisoned by harness).
// ---------------------------------------------------------------------------
__global__ __launch_bounds__(256) void zerofill_kernel(float* __restrict__ out) {
    int i = blockIdx.x;
    int b = blockIdx.y;
    if (g_valid[b * SS + i] != 0.0f) return;
    float4 z = make_float4(0.f, 0.f, 0.f, 0.f);
    *(float4*)(out + (size_t)i * (BB * DD) + (size_t)b * DD + 4 * threadIdx.x) = z;
}

// ---------------------------------------------------------------------------
// K1: fused pred + prob. Block (r, b) = r-th valid output row of batch b.
//   pred = sigmoid(x[i,b,:]·W + bias) * nv,  i = idx[b][r]
//   Ac[b][r][c] = normalized 1/((pred+lang-j_c)^2 + 1e-3) over compacted c.
// ---------------------------------------------------------------------------
__global__ __launch_bounds__(256) void probpred_kernel(
    const float* __restrict__ x, const float* __restrict__ W,
    const float* __restrict__ bias)
{
    int r = blockIdx.x;
    int b = blockIdx.y;
    int nv = g_nv[b];
    if (r >= nv) return;
    int tid = threadIdx.x;

    const int* idxp = g_idx + b * SS;
    int i = idxp[r];

    // ---- inline pred: dot(x[i,b,:], W) with 256 threads x 4 floats ----
    float4 xa = ((const float4*)(x + ((size_t)i * BB + b) * DD))[tid];
    float4 wa = ((const float4*)W)[tid];
    float ds = xa.x * wa.x + xa.y * wa.y + xa.z * wa.z + xa.w * wa.w;

    __shared__ float red[8];
    __shared__ float s_bcast;
#pragma unroll
    for (int o = 16; o; o >>= 1) ds += __shfl_xor_sync(0xFFFFFFFFu, ds, o);
    if ((tid & 31) == 0) red[tid >> 5] = ds;
    __syncthreads();
    if (tid == 0) {
        float s = 0.0f;
#pragma unroll
        for (int wq = 0; wq < 8; wq++) s += red[wq];
        float p = 1.0f / (1.0f + expf(-(s + bias[0])));
        // c0 = pred*slen + lang
        s_bcast = p * (float)nv + (float)(SS - nv);
    }
    __syncthreads();
    float c0 = s_bcast;
    __syncthreads();   // red reuse below

    // ---- prob over compacted columns ----
    int4 ii = ((const int4*)idxp)[tid];
    float v[4];
    float lsum = 0.0f;
#pragma unroll
    for (int t = 0; t < 4; t++) {
        int cpos = 4 * tid + t;
        int jj = (t == 0) ? ii.x : (t == 1) ? ii.y : (t == 2) ? ii.z : ii.w;
        float val = 0.0f;
        if (cpos < nv) {
            float d = c0 - (float)jj;
            val = __fdividef(1.0f, d * d + 0.001f);
        }
        v[t] = val;
        lsum += val;
    }

#pragma unroll
    for (int o = 16; o; o >>= 1) lsum += __shfl_xor_sync(0xFFFFFFFFu, lsum, o);
    if ((tid & 31) == 0) red[tid >> 5] = lsum;
    __syncthreads();
    if (tid == 0) {
        float s = 0.0f;
#pragma unroll
        for (int wq = 0; wq < 8; wq++) s += red[wq];
        s_bcast = __fdividef(1.0f, s);
    }
    __syncthreads();
    float scale = s_bcast;

    __half h[4];
#pragma unroll
    for (int t = 0; t < 4; t++) h[t] = __float2half_rn(v[t] * scale);
    *(uint2*)(g_probH + ((size_t)b * SS + r) * SS + 4 * tid) = *(uint2*)h;
}

// ---------------------------------------------------------------------------
// K2b: gather+transpose pe: peTc[b][d][c] = pe[idx[b][c], b, d] (fp16).
// ---------------------------------------------------------------------------
__global__ __launch_bounds__(256) void gather_kernel(const float* __restrict__ pe) {
    int c0 = blockIdx.x * 64;
    int d0 = blockIdx.y * 64;
    int b  = blockIdx.z;
    int nv = g_nv[b];
    int kceil = ((nv + BK - 1) / BK) * BK;
    if (c0 >= kceil) return;
    int tid = threadIdx.x;

    __shared__ float t[64][65];

#pragma unroll
    for (int q = 0; q < 4; q++) {
        int idx = tid + 256 * q;
        int cc  = idx >> 4;
        int c4  = idx & 15;
        int c   = c0 + cc;
        float4 v = make_float4(0.f, 0.f, 0.f, 0.f);
        if (c < nv) {
            int j = g_idx[b * SS + c];
            v = *(const float4*)(pe + ((size_t)j * BB + b) * DD + d0 + c4 * 4);
        }
        t[cc][c4 * 4 + 0] = v.x;
        t[cc][c4 * 4 + 1] = v.y;
        t[cc][c4 * 4 + 2] = v.z;
        t[cc][c4 * 4 + 3] = v.w;
    }
    __syncthreads();

#pragma unroll
    for (int q = 0; q < 4; q++) {
        int idx = tid + 256 * q;
        int dr  = idx >> 4;
        int c4  = idx & 15;
        __half h[4];
#pragma unroll
        for (int k = 0; k < 4; k++) h[k] = __float2half_rn(t[c4 * 4 + k][dr]);
        size_t dst = ((size_t)b * DD + d0 + dr) * SS + c0 + c4 * 4;
        *(uint2*)&g_peT[dst] = *(uint2*)h;
    }
}

// ---------------------------------------------------------------------------
// K3: compacted batched GEMM, fp16 mma.sync m16n8k16 (fp32 accum).
// ---------------------------------------------------------------------------
__global__ __launch_bounds__(256, 1) void gemm_fp16_kernel(float* __restrict__ out) {
    const int b  = blockIdx.z;
    const int ti = blockIdx.y * MT;
    const int td = blockIdx.x * NT;

    const int nI = g_nv[b];
    if (ti >= nI) return;
    const int kc = (nI + BK - 1) / BK;

    extern __shared__ __half sm[];
    const uint32_t sbase = smem_u32(sm);

    const int tid  = threadIdx.x;
    const int lane = tid & 31;
    const int warp = tid >> 5;
    const int wm   = warp & 1;
    const int wn   = warp >> 1;
    const int gid  = lane >> 2;
    const int tig  = lane & 3;

    const int lrow = lane & 7;
    const int lq   = lane >> 3;
    const int a_off = (lrow + 8 * (lq & 1)) * AST + 8 * (lq >> 1);
    const int b_off = (lrow + 8 * (lq >> 1)) * AST + 8 * (lq & 1);

    const __half* pA = g_probH + ((size_t)b * SS + ti) * SS;
    const __half* pB = g_peT   + ((size_t)b * DD + td) * SS;

    float acc[4][8][4];
#pragma unroll
    for (int mf = 0; mf < 4; mf++)
#pragma unroll
        for (int nf = 0; nf < 8; nf++)
#pragma unroll
            for (int r = 0; r < 4; r++) acc[mf][nf][r] = 0.0f;

    auto load_stage = [&](int kt) {
        const int j0 = kt * BK;
        const uint32_t base = sbase + (uint32_t)((kt & 1) * BUF_HALVES) * 2;
#pragma unroll
        for (int t = 0; t < 4; t++) {
            int idx = tid + 256 * t;
            int row = idx >> 3, c = idx & 7;
            CP_ASYNC16(base + (uint32_t)(row * AST + c * 8) * 2,
                       pA + (size_t)row * SS + j0 + c * 8);
        }
#pragma unroll
        for (int t = 0; t < 8; t++) {
            int idx = tid + 256 * t;
            int row = idx >> 3, c = idx & 7;
            CP_ASYNC16(base + (uint32_t)(A_HALVES + row * AST + c * 8) * 2,
                       pB + (size_t)row * SS + j0 + c * 8);
        }
        CP_COMMIT();
    };

    load_stage(0);

    for (int kt = 0; kt < kc; kt++) {
        if (kt + 1 < kc) {
            load_stage(kt + 1);
            CP_WAIT(1);
        } else {
            CP_WAIT(0);
        }
        __syncthreads();

        const uint32_t abase = sbase + (uint32_t)((kt & 1) * BUF_HALVES) * 2;
        const uint32_t bbase = abase + (uint32_t)A_HALVES * 2;

#pragma unroll
        for (int ks = 0; ks < BK; ks += 16) {
            uint32_t afr[4][4];
#pragma unroll
            for (int mf = 0; mf < 4; mf++) {
                uint32_t ad = abase + (uint32_t)(((wm * 64 + mf * 16) * AST + ks) + a_off) * 2;
                LDSM4(afr[mf][0], afr[mf][1], afr[mf][2], afr[mf][3], ad);
            }
            uint32_t bfr[8][2];
#pragma unroll
            for (int np = 0; np < 4; np++) {
                uint32_t bd = bbase + (uint32_t)(((wn * 64 + np * 16) * AST + ks) + b_off) * 2;
                LDSM4(bfr[2 * np][0], bfr[2 * np][1],
                      bfr[2 * np + 1][0], bfr[2 * np + 1][1], bd);
            }
#pragma unroll
            for (int mf = 0; mf < 4; mf++) {
#pragma unroll
                for (int nf = 0; nf < 8; nf++) {
                    asm volatile(
                        "mma.sync.aligned.m16n8k16.row.col.f32.f16.f16.f32 "
                        "{%0,%1,%2,%3}, {%4,%5,%6,%7}, {%8,%9}, {%0,%1,%2,%3};"
                        : "+f"(acc[mf][nf][0]), "+f"(acc[mf][nf][1]),
                          "+f"(acc[mf][nf][2]), "+f"(acc[mf][nf][3])
                        : "r"(afr[mf][0]), "r"(afr[mf][1]),
                          "r"(afr[mf][2]), "r"(afr[mf][3]),
                        "r"(bfr[nf][0]), "r"(bfr[nf][1]));
                }
            }
        }
        __syncthreads();
    }

    const int* idxp = g_idx + b * SS;
#pragma unroll
    for (int mf = 0; mf < 4; mf++) {
        int r0 = ti + wm * 64 + mf * 16 + gid;
        int r1 = r0 + 8;
        int ig0 = (r0 < nI) ? idxp[r0] : -1;
        int ig1 = (r1 < nI) ? idxp[r1] : -1;
#pragma unroll
        for (int nf = 0; nf < 8; nf++) {
            int col = td + wn * 64 + nf * 8 + tig * 2;
            if (ig0 >= 0)
                *(float2*)(out + (size_t)ig0 * (BB * DD) + (size_t)b * DD + col) =
                    make_float2(acc[mf][nf][0], acc[mf][nf][1]);
            if (ig1 >= 0)
                *(float2*)(out + (size_t)ig1 * (BB * DD) + (size_t)b * DD + col) =
                    make_float2(acc[mf][nf][2], acc[mf][nf][3]);
        }
    }
}

// ---------------------------------------------------------------------------
// Launch: fork-join stream graph.
//   default: mask ─┬─> s1: probpred ──e1─┐
//                  ├─> s2: gather  ──e2─┼─> default: gemm ──┐
//                  └─> s3: zerofill ──e3────────────────────┴─> join
// Events are DisableTiming (graph-capture legal). Streams created/destroyed
// per call (host-side only; no device allocation).
// ---------------------------------------------------------------------------
extern "C" void kernel_launch(void* const* d_in, const int* in_sizes, int n_in,
                              void* d_out, int out_size) {
    const float* x    = (const float*)d_in[0];
    const float* pe   = (const float*)d_in[2];
    const void*  mask = d_in[3];
    const float* W    = (const float*)d_in[4];
    const float* bias = (const float*)d_in[5];
    float*       out  = (float*)d_out;

    cudaFuncSetAttribute(gemm_fp16_kernel,
                         cudaFuncAttributeMaxDynamicSharedMemorySize, GEMM_SMEM);

    cudaStream_t s1, s2, s3;
    cudaStreamCreateWithFlags(&s1, cudaStreamNonBlocking);
    cudaStreamCreateWithFlags(&s2, cudaStreamNonBlocking);
    cudaStreamCreateWithFlags(&s3, cudaStreamNonBlocking);
    cudaEvent_t e0, e1, e2, e3;
    cudaEventCreateWithFlags(&e0, cudaEventDisableTiming);
    cudaEventCreateWithFlags(&e1, cudaEventDisableTiming);
    cudaEventCreateWithFlags(&e2, cudaEventDisableTiming);
    cudaEventCreateWithFlags(&e3, cudaEventDisableTiming);

    mask_kernel<<<BB, 1024>>>(mask);
    cudaEventRecord(e0, 0);
    cudaStreamWaitEvent(s1, e0, 0);
    cudaStreamWaitEvent(s2, e0, 0);
    cudaStreamWaitEvent(s3, e0, 0);

    dim3 pgrid(SS, BB);
    probpred_kernel<<<pgrid, 256, 0, s1>>>(x, W, bias);
    cudaEventRecord(e1, s1);

    dim3 g2(SS / 64, DD / 64, BB);
    gather_kernel<<<g2, 256, 0, s2>>>(pe);
    cudaEventRecord(e2, s2);

    dim3 zgrid(SS, BB);
    zerofill_kernel<<<zgrid, 256, 0, s3>>>(out);
    cudaEventRecord(e3, s3);

    cudaStreamWaitEvent(0, e1, 0);
    cudaStreamWaitEvent(0, e2, 0);

    dim3 ggrid(DD / NT, SS / MT, BB);
    gemm_fp16_kernel<<<ggrid, 256, GEMM_SMEM>>>(out);

    cudaStreamWaitEvent(0, e3, 0);

    cudaEventDestroy(e0);
    cudaEventDestroy(e1);
    cudaEventDestroy(e2);
    cudaEventDestroy(e3);
    cudaStreamDestroy(s1);
    cudaStreamDestroy(s2);
    cudaStreamDestroy(s3);
}

// round 12
// speedup vs baseline: 2.8579x; 1.0474x over previous
#include <cuda_runtime.h>
#include <cuda_bf16.h>
#include <cuda_fp16.h>
#include <math.h>
#include <stdint.h>

// Problem constants
#define SS 1024   // sequence length S
#define BB 32     // batch B
#define DD 1024   // model dim D

// Pipeline groups: 4 groups x 8 batches, on {default, s1, s2, s3}
// (3 created streams + 4 events == the resource budget that passed in R10;
//  8 created streams tripped the 2MB device-memory guard in R11)
#define NGRP 4
#define GB (BB / NGRP)   // batches per group = 8

// GEMM tiling
#define MT 128
#define NT 256
#define BK 64
#define AST 72                        // smem row stride (halves)
#define A_HALVES (128 * AST)
#define B_HALVES (256 * AST)
#define BUF_HALVES (A_HALVES + B_HALVES)
#define GEMM_SMEM (2 * BUF_HALVES * 2)   // bytes, double-buffered

// Scratch (device globals — allocation-guard-safe)
__device__ __half g_probH[(size_t)BB * SS * SS];   // (B, r, c) compacted prob, fp16
__device__ __half g_peT[(size_t)BB * DD * SS];     // (B, d, c) compacted gathered pe, fp16
__device__ int   g_idx[BB * SS];                   // per-batch valid positions
__device__ int   g_inv[BB * SS];                   // per-batch invalid positions
__device__ int   g_nv[BB];                         // per-batch valid count

__device__ __forceinline__ uint32_t smem_u32(const void* p) {
    uint32_t a;
    asm("{ .reg .u64 t; cvta.to.shared.u64 t, %1; cvt.u32.u64 %0, t; }"
        : "=r"(a) : "l"(p));
    return a;
}
#define CP_ASYNC16(dst, src) \
    asm volatile("cp.async.cg.shared.global [%0], [%1], 16;" :: "r"(dst), "l"(src))
#define CP_COMMIT() asm volatile("cp.async.commit_group;" ::: "memory")
#define CP_WAIT(n)  asm volatile("cp.async.wait_group %0;" :: "n"(n) : "memory")
#define LDSM4(r0, r1, r2, r3, a) \
    asm volatile("ldmatrix.sync.aligned.m8n8.x4.shared.b16 {%0,%1,%2,%3}, [%4];" \
                 : "=r"(r0), "=r"(r1), "=r"(r2), "=r"(r3) : "r"(a))

// ---------------------------------------------------------------------------
// K0: mask kernel — inline dtype sniff + dual compaction (valid + invalid).
// One block (1024 thr) per batch.
// ---------------------------------------------------------------------------
__global__ __launch_bounds__(1024) void mask_kernel(const void* __restrict__ maskp) {
    int b = blockIdx.x;
    int j = threadIdx.x;
    int lane = j & 31;
    int w    = j >> 5;

    const int* m32 = (const int*)maskp;
    int any = 0;
#pragma unroll
    for (int t = 0; t < 8; t++) {
        any |= ((unsigned)m32[t * 1024 + j] > 1u) ? 1 : 0;
    }
    int is_u8 = __syncthreads_or(any);

    int mv;
    if (is_u8) mv = ((const unsigned char*)maskp)[b * SS + j];
    else       mv = m32[b * SS + j];
    int valid = (mv == 0) ? 1 : 0;

    unsigned ball = __ballot_sync(0xFFFFFFFFu, valid);
    int rank = __popc(ball & ((1u << lane) - 1));
    int wcnt = __popc(ball);

    __shared__ int wsum[32];
    if (lane == 0) wsum[w] = wcnt;
    __syncthreads();
    if (j < 32) {
        int v = wsum[j];
#pragma unroll
        for (int o = 1; o < 32; o <<= 1) {
            int t = __shfl_up_sync(0xFFFFFFFFu, v, o);
            if (lane >= o) v += t;
        }
        wsum[j] = v;
    }
    __syncthreads();
    int base = (w == 0) ? 0 : wsum[w - 1];
    int vex  = base + rank;                 // exclusive count of valid <= j-1
    if (valid) g_idx[b * SS + vex] = j;
    else       g_inv[b * SS + (j - vex)] = j;

    if (j == 0) g_nv[b] = wsum[31];
}

// ---------------------------------------------------------------------------
// K0b: zero-fill invalid output rows via compacted invalid list.
// Block 1024 thr = 4 rows; grid (SS/4, GB). Work-proportional.
// ---------------------------------------------------------------------------
__global__ __launch_bounds__(1024) void zerofill_kernel(float* __restrict__ out, int b0) {
    int b = b0 + blockIdx.y;
    int ninv = SS - g_nv[b];
    int r = blockIdx.x * 4 + (threadIdx.x >> 8);
    if (r >= ninv) return;
    int i = g_inv[b * SS + r];
    int c = (threadIdx.x & 255) * 4;
    *(float4*)(out + (size_t)i * (BB * DD) + (size_t)b * DD + c) =
        make_float4(0.f, 0.f, 0.f, 0.f);
}

// ---------------------------------------------------------------------------
// K1: fused pred + prob. Block (r, gb): r-th valid output row of batch b0+gb.
// ---------------------------------------------------------------------------
__global__ __launch_bounds__(256) void probpred_kernel(
    const float* __restrict__ x, const float* __restrict__ W,
    const float* __restrict__ bias, int b0)
{
    int r = blockIdx.x;
    int b = b0 + blockIdx.y;
    int nv = g_nv[b];
    if (r >= nv) return;
    int tid = threadIdx.x;

    const int* idxp = g_idx + b * SS;
    int i = idxp[r];

    // ---- inline pred: dot(x[i,b,:], W) ----
    float4 xa = ((const float4*)(x + ((size_t)i * BB + b) * DD))[tid];
    float4 wa = ((const float4*)W)[tid];
    float ds = xa.x * wa.x + xa.y * wa.y + xa.z * wa.z + xa.w * wa.w;

    __shared__ float red[8];
    __shared__ float s_bcast;
#pragma unroll
    for (int o = 16; o; o >>= 1) ds += __shfl_xor_sync(0xFFFFFFFFu, ds, o);
    if ((tid & 31) == 0) red[tid >> 5] = ds;
    __syncthreads();
    if (tid == 0) {
        float s = 0.0f;
#pragma unroll
        for (int wq = 0; wq < 8; wq++) s += red[wq];
        float p = 1.0f / (1.0f + expf(-(s + bias[0])));
        s_bcast = p * (float)nv + (float)(SS - nv);   // c0 = pred*slen + lang
    }
    __syncthreads();
    float c0 = s_bcast;
    __syncthreads();   // red reuse below

    // ---- prob over compacted columns ----
    int4 ii = ((const int4*)idxp)[tid];
    float v[4];
    float lsum = 0.0f;
#pragma unroll
    for (int t = 0; t < 4; t++) {
        int cpos = 4 * tid + t;
        int jj = (t == 0) ? ii.x : (t == 1) ? ii.y : (t == 2) ? ii.z : ii.w;
        float val = 0.0f;
        if (cpos < nv) {
            float d = c0 - (float)jj;
            val = __fdividef(1.0f, d * d + 0.001f);
        }
        v[t] = val;
        lsum += val;
    }

#pragma unroll
    for (int o = 16; o; o >>= 1) lsum += __shfl_xor_sync(0xFFFFFFFFu, lsum, o);
    if ((tid & 31) == 0) red[tid >> 5] = lsum;
    __syncthreads();
    if (tid == 0) {
        float s = 0.0f;
#pragma unroll
        for (int wq = 0; wq < 8; wq++) s += red[wq];
        s_bcast = __fdividef(1.0f, s);
    }
    __syncthreads();
    float scale = s_bcast;

    __half h[4];
#pragma unroll
    for (int t = 0; t < 4; t++) h[t] = __float2half_rn(v[t] * scale);
    *(uint2*)(g_probH + ((size_t)b * SS + r) * SS + 4 * tid) = *(uint2*)h;
}

// ---------------------------------------------------------------------------
// K2: gather+transpose pe: peTc[b][d][c] = pe[idx[b][c], b, d] (fp16).
// ---------------------------------------------------------------------------
__global__ __launch_bounds__(256) void gather_kernel(const float* __restrict__ pe, int b0) {
    int c0 = blockIdx.x * 64;
    int d0 = blockIdx.y * 64;
    int b  = b0 + blockIdx.z;
    int nv = g_nv[b];
    int kceil = ((nv + BK - 1) / BK) * BK;
    if (c0 >= kceil) return;
    int tid = threadIdx.x;

    __shared__ float t[64][65];

#pragma unroll
    for (int q = 0; q < 4; q++) {
        int idx = tid + 256 * q;
        int cc  = idx >> 4;
        int c4  = idx & 15;
        int c   = c0 + cc;
        float4 v = make_float4(0.f, 0.f, 0.f, 0.f);
        if (c < nv) {
            int j = g_idx[b * SS + c];
            v = *(const float4*)(pe + ((size_t)j * BB + b) * DD + d0 + c4 * 4);
        }
        t[cc][c4 * 4 + 0] = v.x;
        t[cc][c4 * 4 + 1] = v.y;
        t[cc][c4 * 4 + 2] = v.z;
        t[cc][c4 * 4 + 3] = v.w;
    }
    __syncthreads();

#pragma unroll
    for (int q = 0; q < 4; q++) {
        int idx = tid + 256 * q;
        int dr  = idx >> 4;
        int c4  = idx & 15;
        __half h[4];
#pragma unroll
        for (int k = 0; k < 4; k++) h[k] = __float2half_rn(t[c4 * 4 + k][dr]);
        size_t dst = ((size_t)b * DD + d0 + dr) * SS + c0 + c4 * 4;
        *(uint2*)&g_peT[dst] = *(uint2*)h;
    }
}

// ---------------------------------------------------------------------------
// K3: compacted batched GEMM, fp16 mma.sync m16n8k16 (fp32 accum).
// ---------------------------------------------------------------------------
__global__ __launch_bounds__(256, 1) void gemm_fp16_kernel(float* __restrict__ out, int b0) {
    const int b  = b0 + blockIdx.z;
    const int ti = blockIdx.y * MT;
    const int td = blockIdx.x * NT;

    const int nI = g_nv[b];
    if (ti >= nI) return;
    const int kc = (nI + BK - 1) / BK;

    extern __shared__ __half sm[];
    const uint32_t sbase = smem_u32(sm);

    const int tid  = threadIdx.x;
    const int lane = tid & 31;
    const int warp = tid >> 5;
    const int wm   = warp & 1;
    const int wn   = warp >> 1;
    const int gid  = lane >> 2;
    const int tig  = lane & 3;

    const int lrow = lane & 7;
    const int lq   = lane >> 3;
    const int a_off = (lrow + 8 * (lq & 1)) * AST + 8 * (lq >> 1);
    const int b_off = (lrow + 8 * (lq >> 1)) * AST + 8 * (lq & 1);

    const __half* pA = g_probH + ((size_t)b * SS + ti) * SS;
    const __half* pB = g_peT   + ((size_t)b * DD + td) * SS;

    float acc[4][8][4];
#pragma unroll
    for (int mf = 0; mf < 4; mf++)
#pragma unroll
        for (int nf = 0; nf < 8; nf++)
#pragma unroll
            for (int r = 0; r < 4; r++) acc[mf][nf][r] = 0.0f;

    auto load_stage = [&](int kt) {
        const int j0 = kt * BK;
        const uint32_t base = sbase + (uint32_t)((kt & 1) * BUF_HALVES) * 2;
#pragma unroll
        for (int t = 0; t < 4; t++) {
            int idx = tid + 256 * t;
            int row = idx >> 3, c = idx & 7;
            CP_ASYNC16(base + (uint32_t)(row * AST + c * 8) * 2,
                       pA + (size_t)row * SS + j0 + c * 8);
        }
#pragma unroll
        for (int t = 0; t < 8; t++) {
            int idx = tid + 256 * t;
            int row = idx >> 3, c = idx & 7;
            CP_ASYNC16(base + (uint32_t)(A_HALVES + row * AST + c * 8) * 2,
                       pB + (size_t)row * SS + j0 + c * 8);
        }
        CP_COMMIT();
    };

    load_stage(0);

    for (int kt = 0; kt < kc; kt++) {
        if (kt + 1 < kc) {
            load_stage(kt + 1);
            CP_WAIT(1);
        } else {
            CP_WAIT(0);
        }
        __syncthreads();

        const uint32_t abase = sbase + (uint32_t)((kt & 1) * BUF_HALVES) * 2;
        const uint32_t bbase = abase + (uint32_t)A_HALVES * 2;

#pragma unroll
        for (int ks = 0; ks < BK; ks += 16) {
            uint32_t afr[4][4];
#pragma unroll
            for (int mf = 0; mf < 4; mf++) {
                uint32_t ad = abase + (uint32_t)(((wm * 64 + mf * 16) * AST + ks) + a_off) * 2;
                LDSM4(afr[mf][0], afr[mf][1], afr[mf][2], afr[mf][3], ad);
            }
            uint32_t bfr[8][2];
#pragma unroll
            for (int np = 0; np < 4; np++) {
                uint32_t bd = bbase + (uint32_t)(((wn * 64 + np * 16) * AST + ks) + b_off) * 2;
                LDSM4(bfr[2 * np][0], bfr[2 * np][1],
                      bfr[2 * np + 1][0], bfr[2 * np + 1][1], bd);
            }
#pragma unroll
            for (int mf = 0; mf < 4; mf++) {
#pragma unroll
                for (int nf = 0; nf < 8; nf++) {
                    asm volatile(
                        "mma.sync.aligned.m16n8k16.row.col.f32.f16.f16.f32 "
                        "{%0,%1,%2,%3}, {%4,%5,%6,%7}, {%8,%9}, {%0,%1,%2,%3};"
                        : "+f"(acc[mf][nf][0]), "+f"(acc[mf][nf][1]),
                          "+f"(acc[mf][nf][2]), "+f"(acc[mf][nf][3])
                        : "r"(afr[mf][0]), "r"(afr[mf][1]),
                          "r"(afr[mf][2]), "r"(afr[mf][3]),
                        "r"(bfr[nf][0]), "r"(bfr[nf][1]));
                }
            }
        }
        __syncthreads();
    }

    const int* idxp = g_idx + b * SS;
#pragma unroll
    for (int mf = 0; mf < 4; mf++) {
        int r0 = ti + wm * 64 + mf * 16 + gid;
        int r1 = r0 + 8;
        int ig0 = (r0 < nI) ? idxp[r0] : -1;
        int ig1 = (r1 < nI) ? idxp[r1] : -1;
#pragma unroll
        for (int nf = 0; nf < 8; nf++) {
            int col = td + wn * 64 + nf * 8 + tig * 2;
            if (ig0 >= 0)
                *(float2*)(out + (size_t)ig0 * (BB * DD) + (size_t)b * DD + col) =
                    make_float2(acc[mf][nf][0], acc[mf][nf][1]);
            if (ig1 >= 0)
                *(float2*)(out + (size_t)ig1 * (BB * DD) + (size_t)b * DD + col) =
                    make_float2(acc[mf][nf][2], acc[mf][nf][3]);
        }
    }
}

// ---------------------------------------------------------------------------
// Launch: 4-way per-batch-group pipeline.
// Pipeline 0 runs on the default stream; pipelines 1-3 on created streams.
// Resource budget: 3 streams + 4 events (matches the R10-passing footprint).
// ---------------------------------------------------------------------------
extern "C" void kernel_launch(void* const* d_in, const int* in_sizes, int n_in,
                              void* d_out, int out_size) {
    const float* x    = (const float*)d_in[0];
    const float* pe   = (const float*)d_in[2];
    const void*  mask = d_in[3];
    const float* W    = (const float*)d_in[4];
    const float* bias = (const float*)d_in[5];
    float*       out  = (float*)d_out;

    cudaFuncSetAttribute(gemm_fp16_kernel,
                         cudaFuncAttributeMaxDynamicSharedMemorySize, GEMM_SMEM);

    cudaStream_t sx[3];
    cudaEvent_t  ev[3];
    cudaEvent_t  e0;
    cudaEventCreateWithFlags(&e0, cudaEventDisableTiming);
    for (int g = 0; g < 3; g++) {
        cudaStreamCreateWithFlags(&sx[g], cudaStreamNonBlocking);
        cudaEventCreateWithFlags(&ev[g], cudaEventDisableTiming);
    }

    mask_kernel<<<BB, 1024>>>(mask);
    cudaEventRecord(e0, 0);

    for (int g = 0; g < NGRP; g++) {
        int b0 = g * GB;
        cudaStream_t s = (g == 0) ? (cudaStream_t)0 : sx[g - 1];
        if (g != 0) cudaStreamWaitEvent(s, e0, 0);

        dim3 pgrid(SS, GB);
        probpred_kernel<<<pgrid, 256, 0, s>>>(x, W, bias, b0);

        dim3 g2(SS / 64, DD / 64, GB);
        gather_kernel<<<g2, 256, 0, s>>>(pe, b0);

        dim3 ggrid(DD / NT, SS / MT, GB);
        gemm_fp16_kernel<<<ggrid, 256, GEMM_SMEM, s>>>(out, b0);

        dim3 zgrid(SS / 4, GB);
        zerofill_kernel<<<zgrid, 1024, 0, s>>>(out, b0);

        if (g != 0) cudaEventRecord(ev[g - 1], s);
    }
    for (int g = 0; g < 3; g++) cudaStreamWaitEvent(0, ev[g], 0);

    cudaEventDestroy(e0);
    for (int g = 0; g < 3; g++) {
        cudaEventDestroy(ev[g]);
        cudaStreamDestroy(sx[g]);
    }
}

// round 13
// speedup vs baseline: 2.8603x; 1.0009x over previous
#include <cuda_runtime.h>
#include <cuda_bf16.h>
#include <cuda_fp16.h>
#include <math.h>
#include <stdint.h>

// Problem constants
#define SS 1024   // sequence length S
#define BB 32     // batch B
#define DD 1024   // model dim D

// Pipeline groups: 4 groups x 8 batches on {default, s1, s2, s3}
#define NGRP 4
#define GB (BB / NGRP)   // 8

// GEMM tiling
#define MT 128
#define NT 256
#define BK 64
#define NSTAGE 3
#define AST 72                        // smem row stride (halves)
#define A_HALVES (128 * AST)
#define B_HALVES (256 * AST)
#define BUF_HALVES (A_HALVES + B_HALVES)
#define GEMM_SMEM (NSTAGE * BUF_HALVES * 2)   // bytes, triple-buffered

// Scratch (device globals — allocation-guard-safe)
__device__ __half g_probH[(size_t)BB * SS * SS];   // (B, r, c) compacted prob, fp16
__device__ __half g_peT[(size_t)BB * DD * SS];     // (B, d, c) compacted gathered pe, fp16
__device__ int   g_idx[BB * SS];                   // per-batch valid positions
__device__ int   g_inv[BB * SS];                   // per-batch invalid positions
__device__ int   g_nv[BB];                         // per-batch valid count

__device__ __forceinline__ uint32_t smem_u32(const void* p) {
    uint32_t a;
    asm("{ .reg .u64 t; cvta.to.shared.u64 t, %1; cvt.u32.u64 %0, t; }"
        : "=r"(a) : "l"(p));
    return a;
}
#define CP_ASYNC16(dst, src) \
    asm volatile("cp.async.cg.shared.global [%0], [%1], 16;" :: "r"(dst), "l"(src))
#define CP_COMMIT() asm volatile("cp.async.commit_group;" ::: "memory")
#define CP_WAIT(n)  asm volatile("cp.async.wait_group %0;" :: "n"(n) : "memory")
#define LDSM4(r0, r1, r2, r3, a) \
    asm volatile("ldmatrix.sync.aligned.m8n8.x4.shared.b16 {%0,%1,%2,%3}, [%4];" \
                 : "=r"(r0), "=r"(r1), "=r"(r2), "=r"(r3) : "r"(a))

// ---------------------------------------------------------------------------
// K0: mask kernel — inline dtype sniff + dual compaction (valid + invalid).
// ---------------------------------------------------------------------------
__global__ __launch_bounds__(1024) void mask_kernel(const void* __restrict__ maskp) {
    int b = blockIdx.x;
    int j = threadIdx.x;
    int lane = j & 31;
    int w    = j >> 5;

    const int* m32 = (const int*)maskp;
    int any = 0;
#pragma unroll
    for (int t = 0; t < 8; t++) {
        any |= ((unsigned)m32[t * 1024 + j] > 1u) ? 1 : 0;
    }
    int is_u8 = __syncthreads_or(any);

    int mv;
    if (is_u8) mv = ((const unsigned char*)maskp)[b * SS + j];
    else       mv = m32[b * SS + j];
    int valid = (mv == 0) ? 1 : 0;

    unsigned ball = __ballot_sync(0xFFFFFFFFu, valid);
    int rank = __popc(ball & ((1u << lane) - 1));
    int wcnt = __popc(ball);

    __shared__ int wsum[32];
    if (lane == 0) wsum[w] = wcnt;
    __syncthreads();
    if (j < 32) {
        int v = wsum[j];
#pragma unroll
        for (int o = 1; o < 32; o <<= 1) {
            int t = __shfl_up_sync(0xFFFFFFFFu, v, o);
            if (lane >= o) v += t;
        }
        wsum[j] = v;
    }
    __syncthreads();
    int base = (w == 0) ? 0 : wsum[w - 1];
    int vex  = base + rank;
    if (valid) g_idx[b * SS + vex] = j;
    else       g_inv[b * SS + (j - vex)] = j;

    if (j == 0) g_nv[b] = wsum[31];
}

// ---------------------------------------------------------------------------
// K0b: zero-fill invalid output rows via compacted invalid list.
// ---------------------------------------------------------------------------
__global__ __launch_bounds__(1024) void zerofill_kernel(float* __restrict__ out, int b0) {
    int b = b0 + blockIdx.y;
    int ninv = SS - g_nv[b];
    int r = blockIdx.x * 4 + (threadIdx.x >> 8);
    if (r >= ninv) return;
    int i = g_inv[b * SS + r];
    int c = (threadIdx.x & 255) * 4;
    *(float4*)(out + (size_t)i * (BB * DD) + (size_t)b * DD + c) =
        make_float4(0.f, 0.f, 0.f, 0.f);
}

// ---------------------------------------------------------------------------
// K1: fused pred + prob. Block (r, gb): r-th valid output row of batch b0+gb.
// ---------------------------------------------------------------------------
__global__ __launch_bounds__(256) void probpred_kernel(
    const float* __restrict__ x, const float* __restrict__ W,
    const float* __restrict__ bias, int b0)
{
    int r = blockIdx.x;
    int b = b0 + blockIdx.y;
    int nv = g_nv[b];
    if (r >= nv) return;
    int tid = threadIdx.x;

    const int* idxp = g_idx + b * SS;
    int i = idxp[r];

    float4 xa = ((const float4*)(x + ((size_t)i * BB + b) * DD))[tid];
    float4 wa = ((const float4*)W)[tid];
    float ds = xa.x * wa.x + xa.y * wa.y + xa.z * wa.z + xa.w * wa.w;

    __shared__ float red[8];
    __shared__ float s_bcast;
#pragma unroll
    for (int o = 16; o; o >>= 1) ds += __shfl_xor_sync(0xFFFFFFFFu, ds, o);
    if ((tid & 31) == 0) red[tid >> 5] = ds;
    __syncthreads();
    if (tid == 0) {
        float s = 0.0f;
#pragma unroll
        for (int wq = 0; wq < 8; wq++) s += red[wq];
        float p = 1.0f / (1.0f + expf(-(s + bias[0])));
        s_bcast = p * (float)nv + (float)(SS - nv);   // c0 = pred*slen + lang
    }
    __syncthreads();
    float c0 = s_bcast;
    __syncthreads();

    int4 ii = ((const int4*)idxp)[tid];
    float v[4];
    float lsum = 0.0f;
#pragma unroll
    for (int t = 0; t < 4; t++) {
        int cpos = 4 * tid + t;
        int jj = (t == 0) ? ii.x : (t == 1) ? ii.y : (t == 2) ? ii.z : ii.w;
        float val = 0.0f;
        if (cpos < nv) {
            float d = c0 - (float)jj;
            val = __fdividef(1.0f, d * d + 0.001f);
        }
        v[t] = val;
        lsum += val;
    }

#pragma unroll
    for (int o = 16; o; o >>= 1) lsum += __shfl_xor_sync(0xFFFFFFFFu, lsum, o);
    if ((tid & 31) == 0) red[tid >> 5] = lsum;
    __syncthreads();
    if (tid == 0) {
        float s = 0.0f;
#pragma unroll
        for (int wq = 0; wq < 8; wq++) s += red[wq];
        s_bcast = __fdividef(1.0f, s);
    }
    __syncthreads();
    float scale = s_bcast;

    __half h[4];
#pragma unroll
    for (int t = 0; t < 4; t++) h[t] = __float2half_rn(v[t] * scale);
    *(uint2*)(g_probH + ((size_t)b * SS + r) * SS + 4 * tid) = *(uint2*)h;
}

// ---------------------------------------------------------------------------
// K2: gather+transpose pe: peTc[b][d][c] = pe[idx[b][c], b, d] (fp16).
// ---------------------------------------------------------------------------
__global__ __launch_bounds__(256) void gather_kernel(const float* __restrict__ pe, int b0) {
    int c0 = blockIdx.x * 64;
    int d0 = blockIdx.y * 64;
    int b  = b0 + blockIdx.z;
    int nv = g_nv[b];
    int kceil = ((nv + BK - 1) / BK) * BK;
    if (c0 >= kceil) return;
    int tid = threadIdx.x;

    __shared__ float t[64][65];

#pragma unroll
    for (int q = 0; q < 4; q++) {
        int idx = tid + 256 * q;
        int cc  = idx >> 4;
        int c4  = idx & 15;
        int c   = c0 + cc;
        float4 v = make_float4(0.f, 0.f, 0.f, 0.f);
        if (c < nv) {
            int j = g_idx[b * SS + c];
            v = *(const float4*)(pe + ((size_t)j * BB + b) * DD + d0 + c4 * 4);
        }
        t[cc][c4 * 4 + 0] = v.x;
        t[cc][c4 * 4 + 1] = v.y;
        t[cc][c4 * 4 + 2] = v.z;
        t[cc][c4 * 4 + 3] = v.w;
    }
    __syncthreads();

#pragma unroll
    for (int q = 0; q < 4; q++) {
        int idx = tid + 256 * q;
        int dr  = idx >> 4;
        int c4  = idx & 15;
        __half h[4];
#pragma unroll
        for (int k = 0; k < 4; k++) h[k] = __float2half_rn(t[c4 * 4 + k][dr]);
        size_t dst = ((size_t)b * DD + d0 + dr) * SS + c0 + c4 * 4;
        *(uint2*)&g_peT[dst] = *(uint2*)h;
    }
}

// ---------------------------------------------------------------------------
// K3: compacted batched GEMM, fp16 mma.sync m16n8k16 (fp32 accum).
// 3-stage cp.async pipeline, ONE __syncthreads per K-chunk; next-stage load
// issued before the MMA block so LDGSTS overlaps tensor work.
// ---------------------------------------------------------------------------
__global__ __launch_bounds__(256, 1) void gemm_fp16_kernel(float* __restrict__ out, int b0) {
    const int b  = b0 + blockIdx.z;
    const int ti = blockIdx.y * MT;
    const int td = blockIdx.x * NT;

    const int nI = g_nv[b];
    if (ti >= nI) return;
    const int kc = (nI + BK - 1) / BK;

    extern __shared__ __half sm[];
    const uint32_t sbase = smem_u32(sm);

    const int tid  = threadIdx.x;
    const int lane = tid & 31;
    const int warp = tid >> 5;
    const int wm   = warp & 1;
    const int wn   = warp >> 1;
    const int gid  = lane >> 2;
    const int tig  = lane & 3;

    const int lrow = lane & 7;
    const int lq   = lane >> 3;
    const int a_off = (lrow + 8 * (lq & 1)) * AST + 8 * (lq >> 1);
    const int b_off = (lrow + 8 * (lq >> 1)) * AST + 8 * (lq & 1);

    const __half* pA = g_probH + ((size_t)b * SS + ti) * SS;
    const __half* pB = g_peT   + ((size_t)b * DD + td) * SS;

    float acc[4][8][4];
#pragma unroll
    for (int mf = 0; mf < 4; mf++)
#pragma unroll
        for (int nf = 0; nf < 8; nf++)
#pragma unroll
            for (int r = 0; r < 4; r++) acc[mf][nf][r] = 0.0f;

    auto load_stage = [&](int kt) {
        const int j0 = kt * BK;
        const uint32_t base = sbase + (uint32_t)((kt % NSTAGE) * BUF_HALVES) * 2;
#pragma unroll
        for (int t = 0; t < 4; t++) {
            int idx = tid + 256 * t;
            int row = idx >> 3, c = idx & 7;
            CP_ASYNC16(base + (uint32_t)(row * AST + c * 8) * 2,
                       pA + (size_t)row * SS + j0 + c * 8);
        }
#pragma unroll
        for (int t = 0; t < 8; t++) {
            int idx = tid + 256 * t;
            int row = idx >> 3, c = idx & 7;
            CP_ASYNC16(base + (uint32_t)(A_HALVES + row * AST + c * 8) * 2,
                       pB + (size_t)row * SS + j0 + c * 8);
        }
        CP_COMMIT();
    };

    // Prologue: fill 2 of 3 stages.
    load_stage(0);
    if (kc > 1) load_stage(1);

    for (int kt = 0; kt < kc; kt++) {
        // Stage kt must be complete. Younger in-flight: at most stage kt+1.
        if (kt + 1 < kc) { CP_WAIT(1); } else { CP_WAIT(0); }
        __syncthreads();   // data visibility + proves buffer (kt+2)%3 is free

        if (kt + 2 < kc) load_stage(kt + 2);   // overlaps the MMAs below

        const uint32_t abase = sbase + (uint32_t)((kt % NSTAGE) * BUF_HALVES) * 2;
        const uint32_t bbase = abase + (uint32_t)A_HALVES * 2;

#pragma unroll
        for (int ks = 0; ks < BK; ks += 16) {
            uint32_t afr[4][4];
#pragma unroll
            for (int mf = 0; mf < 4; mf++) {
                uint32_t ad = abase + (uint32_t)(((wm * 64 + mf * 16) * AST + ks) + a_off) * 2;
                LDSM4(afr[mf][0], afr[mf][1], afr[mf][2], afr[mf][3], ad);
            }
            uint32_t bfr[8][2];
#pragma unroll
            for (int np = 0; np < 4; np++) {
                uint32_t bd = bbase + (uint32_t)(((wn * 64 + np * 16) * AST + ks) + b_off) * 2;
                LDSM4(bfr[2 * np][0], bfr[2 * np][1],
                      bfr[2 * np + 1][0], bfr[2 * np + 1][1], bd);
            }
#pragma unroll
            for (int mf = 0; mf < 4; mf++) {
#pragma unroll
                for (int nf = 0; nf < 8; nf++) {
                    asm volatile(
                        "mma.sync.aligned.m16n8k16.row.col.f32.f16.f16.f32 "
                        "{%0,%1,%2,%3}, {%4,%5,%6,%7}, {%8,%9}, {%0,%1,%2,%3};"
                        : "+f"(acc[mf][nf][0]), "+f"(acc[mf][nf][1]),
                          "+f"(acc[mf][nf][2]), "+f"(acc[mf][nf][3])
                        : "r"(afr[mf][0]), "r"(afr[mf][1]),
                          "r"(afr[mf][2]), "r"(afr[mf][3]),
                        "r"(bfr[nf][0]), "r"(bfr[nf][1]));
                }
            }
        }
    }

    const int* idxp = g_idx + b * SS;
#pragma unroll
    for (int mf = 0; mf < 4; mf++) {
        int r0 = ti + wm * 64 + mf * 16 + gid;
        int r1 = r0 + 8;
        int ig0 = (r0 < nI) ? idxp[r0] : -1;
        int ig1 = (r1 < nI) ? idxp[r1] : -1;
#pragma unroll
        for (int nf = 0; nf < 8; nf++) {
            int col = td + wn * 64 + nf * 8 + tig * 2;
            if (ig0 >= 0)
                *(float2*)(out + (size_t)ig0 * (BB * DD) + (size_t)b * DD + col) =
                    make_float2(acc[mf][nf][0], acc[mf][nf][1]);
            if (ig1 >= 0)
                *(float2*)(out + (size_t)ig1 * (BB * DD) + (size_t)b * DD + col) =
                    make_float2(acc[mf][nf][2], acc[mf][nf][3]);
        }
    }
}

// ---------------------------------------------------------------------------
// Launch: 4-way per-batch-group pipeline (3 streams + 4 events, R10 budget).
// ---------------------------------------------------------------------------
extern "C" void kernel_launch(void* const* d_in, const int* in_sizes, int n_in,
                              void* d_out, int out_size) {
    const float* x    = (const float*)d_in[0];
    const float* pe   = (const float*)d_in[2];
    const void*  mask = d_in[3];
    const float* W    = (const float*)d_in[4];
    const float* bias = (const float*)d_in[5];
    float*       out  = (float*)d_out;

    cudaFuncSetAttribute(gemm_fp16_kernel,
                         cudaFuncAttributeMaxDynamicSharedMemorySize, GEMM_SMEM);

    cudaStream_t sx[3];
    cudaEvent_t  ev[3];
    cudaEvent_t  e0;
    cudaEventCreateWithFlags(&e0, cudaEventDisableTiming);
    for (int g = 0; g < 3; g++) {
        cudaStreamCreateWithFlags(&sx[g], cudaStreamNonBlocking);
        cudaEventCreateWithFlags(&ev[g], cudaEventDisableTiming);
    }

    mask_kernel<<<BB, 1024>>>(mask);
    cudaEventRecord(e0, 0);

    for (int g = 0; g < NGRP; g++) {
        int b0 = g * GB;
        cudaStream_t s = (g == 0) ? (cudaStream_t)0 : sx[g - 1];
        if (g != 0) cudaStreamWaitEvent(s, e0, 0);

        dim3 pgrid(SS, GB);
        probpred_kernel<<<pgrid, 256, 0, s>>>(x, W, bias, b0);

        dim3 g2(SS / 64, DD / 64, GB);
        gather_kernel<<<g2, 256, 0, s>>>(pe, b0);

        dim3 ggrid(DD / NT, SS / MT, GB);
        gemm_fp16_kernel<<<ggrid, 256, GEMM_SMEM, s>>>(out, b0);

        dim3 zgrid(SS / 4, GB);
        zerofill_kernel<<<zgrid, 1024, 0, s>>>(out, b0);

        if (g != 0) cudaEventRecord(ev[g - 1], s);
    }
    for (int g = 0; g < 3; g++) cudaStreamWaitEvent(0, ev[g], 0);

    cudaEventDestroy(e0);
    for (int g = 0; g < 3; g++) {
        cudaEventDestroy(ev[g]);
        cudaStreamDestroy(sx[g]);
    }
}

// round 14
// speedup vs baseline: 3.0670x; 1.0723x over previous
#include <cuda_runtime.h>
#include <cuda_bf16.h>
#include <cuda_fp16.h>
#include <math.h>
#include <stdint.h>

// Problem constants
#define SS 1024   // sequence length S
#define BB 32     // batch B
#define DD 1024   // model dim D

// Pipeline groups: 4 groups x 8 batches on {default, s1, s2, s3}
#define NGRP 4
#define GB (BB / NGRP)   // 8

// GEMM tiling: 128x128 block tile, 2 CTAs/SM (reg-capped), 2-stage cp.async
#define MT 128
#define NT 128
#define BK 64
#define NSTAGE 2
#define AST 72                        // smem row stride (halves)
#define A_HALVES (128 * AST)
#define B_HALVES (128 * AST)
#define BUF_HALVES (A_HALVES + B_HALVES)
#define GEMM_SMEM (NSTAGE * BUF_HALVES * 2)   // 73728 bytes

// Scratch (device globals — allocation-guard-safe)
__device__ __half g_probH[(size_t)BB * SS * SS];   // (B, r, c) compacted prob, fp16
__device__ __half g_peT[(size_t)BB * DD * SS];     // (B, d, c) compacted gathered pe, fp16
__device__ int   g_idx[BB * SS];                   // per-batch valid positions
__device__ int   g_inv[BB * SS];                   // per-batch invalid positions
__device__ int   g_nv[BB];                         // per-batch valid count

__device__ __forceinline__ uint32_t smem_u32(const void* p) {
    uint32_t a;
    asm("{ .reg .u64 t; cvta.to.shared.u64 t, %1; cvt.u32.u64 %0, t; }"
        : "=r"(a) : "l"(p));
    return a;
}
#define CP_ASYNC16(dst, src) \
    asm volatile("cp.async.cg.shared.global [%0], [%1], 16;" :: "r"(dst), "l"(src))
#define CP_COMMIT() asm volatile("cp.async.commit_group;" ::: "memory")
#define CP_WAIT(n)  asm volatile("cp.async.wait_group %0;" :: "n"(n) : "memory")
#define LDSM4(r0, r1, r2, r3, a) \
    asm volatile("ldmatrix.sync.aligned.m8n8.x4.shared.b16 {%0,%1,%2,%3}, [%4];" \
                 : "=r"(r0), "=r"(r1), "=r"(r2), "=r"(r3) : "r"(a))

// ---------------------------------------------------------------------------
// K0: mask kernel — inline dtype sniff + dual compaction (valid + invalid).
// ---------------------------------------------------------------------------
__global__ __launch_bounds__(1024) void mask_kernel(const void* __restrict__ maskp) {
    int b = blockIdx.x;
    int j = threadIdx.x;
    int lane = j & 31;
    int w    = j >> 5;

    const int* m32 = (const int*)maskp;
    int any = 0;
#pragma unroll
    for (int t = 0; t < 8; t++) {
        any |= ((unsigned)m32[t * 1024 + j] > 1u) ? 1 : 0;
    }
    int is_u8 = __syncthreads_or(any);

    int mv;
    if (is_u8) mv = ((const unsigned char*)maskp)[b * SS + j];
    else       mv = m32[b * SS + j];
    int valid = (mv == 0) ? 1 : 0;

    unsigned ball = __ballot_sync(0xFFFFFFFFu, valid);
    int rank = __popc(ball & ((1u << lane) - 1));
    int wcnt = __popc(ball);

    __shared__ int wsum[32];
    if (lane == 0) wsum[w] = wcnt;
    __syncthreads();
    if (j < 32) {
        int v = wsum[j];
#pragma unroll
        for (int o = 1; o < 32; o <<= 1) {
            int t = __shfl_up_sync(0xFFFFFFFFu, v, o);
            if (lane >= o) v += t;
        }
        wsum[j] = v;
    }
    __syncthreads();
    int base = (w == 0) ? 0 : wsum[w - 1];
    int vex  = base + rank;
    if (valid) g_idx[b * SS + vex] = j;
    else       g_inv[b * SS + (j - vex)] = j;

    if (j == 0) g_nv[b] = wsum[31];
}

// ---------------------------------------------------------------------------
// K0b: zero-fill invalid output rows via compacted invalid list.
// ---------------------------------------------------------------------------
__global__ __launch_bounds__(1024) void zerofill_kernel(float* __restrict__ out, int b0) {
    int b = b0 + blockIdx.y;
    int ninv = SS - g_nv[b];
    int r = blockIdx.x * 4 + (threadIdx.x >> 8);
    if (r >= ninv) return;
    int i = g_inv[b * SS + r];
    int c = (threadIdx.x & 255) * 4;
    *(float4*)(out + (size_t)i * (BB * DD) + (size_t)b * DD + c) =
        make_float4(0.f, 0.f, 0.f, 0.f);
}

// ---------------------------------------------------------------------------
// K1: fused pred + prob. Block (r, gb): r-th valid output row of batch b0+gb.
// ---------------------------------------------------------------------------
__global__ __launch_bounds__(256) void probpred_kernel(
    const float* __restrict__ x, const float* __restrict__ W,
    const float* __restrict__ bias, int b0)
{
    int r = blockIdx.x;
    int b = b0 + blockIdx.y;
    int nv = g_nv[b];
    if (r >= nv) return;
    int tid = threadIdx.x;

    const int* idxp = g_idx + b * SS;
    int i = idxp[r];

    float4 xa = ((const float4*)(x + ((size_t)i * BB + b) * DD))[tid];
    float4 wa = ((const float4*)W)[tid];
    float ds = xa.x * wa.x + xa.y * wa.y + xa.z * wa.z + xa.w * wa.w;

    __shared__ float red[8];
    __shared__ float s_bcast;
#pragma unroll
    for (int o = 16; o; o >>= 1) ds += __shfl_xor_sync(0xFFFFFFFFu, ds, o);
    if ((tid & 31) == 0) red[tid >> 5] = ds;
    __syncthreads();
    if (tid == 0) {
        float s = 0.0f;
#pragma unroll
        for (int wq = 0; wq < 8; wq++) s += red[wq];
        float p = 1.0f / (1.0f + expf(-(s + bias[0])));
        s_bcast = p * (float)nv + (float)(SS - nv);   // c0 = pred*slen + lang
    }
    __syncthreads();
    float c0 = s_bcast;
    __syncthreads();

    int4 ii = ((const int4*)idxp)[tid];
    float v[4];
    float lsum = 0.0f;
#pragma unroll
    for (int t = 0; t < 4; t++) {
        int cpos = 4 * tid + t;
        int jj = (t == 0) ? ii.x : (t == 1) ? ii.y : (t == 2) ? ii.z : ii.w;
        float val = 0.0f;
        if (cpos < nv) {
            float d = c0 - (float)jj;
            val = __fdividef(1.0f, d * d + 0.001f);
        }
        v[t] = val;
        lsum += val;
    }

#pragma unroll
    for (int o = 16; o; o >>= 1) lsum += __shfl_xor_sync(0xFFFFFFFFu, lsum, o);
    if ((tid & 31) == 0) red[tid >> 5] = lsum;
    __syncthreads();
    if (tid == 0) {
        float s = 0.0f;
#pragma unroll
        for (int wq = 0; wq < 8; wq++) s += red[wq];
        s_bcast = __fdividef(1.0f, s);
    }
    __syncthreads();
    float scale = s_bcast;

    __half h[4];
#pragma unroll
    for (int t = 0; t < 4; t++) h[t] = __float2half_rn(v[t] * scale);
    *(uint2*)(g_probH + ((size_t)b * SS + r) * SS + 4 * tid) = *(uint2*)h;
}

// ---------------------------------------------------------------------------
// K2: gather+transpose pe: peTc[b][d][c] = pe[idx[b][c], b, d] (fp16).
// ---------------------------------------------------------------------------
__global__ __launch_bounds__(256) void gather_kernel(const float* __restrict__ pe, int b0) {
    int c0 = blockIdx.x * 64;
    int d0 = blockIdx.y * 64;
    int b  = b0 + blockIdx.z;
    int nv = g_nv[b];
    int kceil = ((nv + BK - 1) / BK) * BK;
    if (c0 >= kceil) return;
    int tid = threadIdx.x;

    __shared__ float t[64][65];

#pragma unroll
    for (int q = 0; q < 4; q++) {
        int idx = tid + 256 * q;
        int cc  = idx >> 4;
        int c4  = idx & 15;
        int c   = c0 + cc;
        float4 v = make_float4(0.f, 0.f, 0.f, 0.f);
        if (c < nv) {
            int j = g_idx[b * SS + c];
            v = *(const float4*)(pe + ((size_t)j * BB + b) * DD + d0 + c4 * 4);
        }
        t[cc][c4 * 4 + 0] = v.x;
        t[cc][c4 * 4 + 1] = v.y;
        t[cc][c4 * 4 + 2] = v.z;
        t[cc][c4 * 4 + 3] = v.w;
    }
    __syncthreads();

#pragma unroll
    for (int q = 0; q < 4; q++) {
        int idx = tid + 256 * q;
        int dr  = idx >> 4;
        int c4  = idx & 15;
        __half h[4];
#pragma unroll
        for (int k = 0; k < 4; k++) h[k] = __float2half_rn(t[c4 * 4 + k][dr]);
        size_t dst = ((size_t)b * DD + d0 + dr) * SS + c0 + c4 * 4;
        *(uint2*)&g_peT[dst] = *(uint2*)h;
    }
}

// ---------------------------------------------------------------------------
// K3: compacted batched GEMM, fp16 mma.sync m16n8k16 (fp32 accum).
// Block tile 128x128, warp tile 64x32 (8 warps, 2m x 4n), 2-stage cp.async,
// __launch_bounds__(256, 2) => <=128 regs/thread => 2 CTAs/SM (16 warps/SM).
// ---------------------------------------------------------------------------
__global__ __launch_bounds__(256, 2) void gemm_fp16_kernel(float* __restrict__ out, int b0) {
    const int b  = b0 + blockIdx.z;
    const int ti = blockIdx.y * MT;
    const int td = blockIdx.x * NT;

    const int nI = g_nv[b];
    if (ti >= nI) return;
    const int kc = (nI + BK - 1) / BK;

    extern __shared__ __half sm[];
    const uint32_t sbase = smem_u32(sm);

    const int tid  = threadIdx.x;
    const int lane = tid & 31;
    const int warp = tid >> 5;
    const int wm   = warp & 1;        // 0..1 (M)
    const int wn   = warp >> 1;       // 0..3 (N)
    const int gid  = lane >> 2;
    const int tig  = lane & 3;

    const int lrow = lane & 7;
    const int lq   = lane >> 3;
    const int a_off = (lrow + 8 * (lq & 1)) * AST + 8 * (lq >> 1);
    const int b_off = (lrow + 8 * (lq >> 1)) * AST + 8 * (lq & 1);

    const __half* pA = g_probH + ((size_t)b * SS + ti) * SS;
    const __half* pB = g_peT   + ((size_t)b * DD + td) * SS;

    float acc[4][4][4];
#pragma unroll
    for (int mf = 0; mf < 4; mf++)
#pragma unroll
        for (int nf = 0; nf < 4; nf++)
#pragma unroll
            for (int r = 0; r < 4; r++) acc[mf][nf][r] = 0.0f;

    auto load_stage = [&](int kt) {
        const int j0 = kt * BK;
        const uint32_t base = sbase + (uint32_t)((kt & 1) * BUF_HALVES) * 2;
#pragma unroll
        for (int t = 0; t < 4; t++) {                 // A: 128 rows x 8 chunks
            int idx = tid + 256 * t;
            int row = idx >> 3, c = idx & 7;
            CP_ASYNC16(base + (uint32_t)(row * AST + c * 8) * 2,
                       pA + (size_t)row * SS + j0 + c * 8);
        }
#pragma unroll
        for (int t = 0; t < 4; t++) {                 // B: 128 rows x 8 chunks
            int idx = tid + 256 * t;
            int row = idx >> 3, c = idx & 7;
            CP_ASYNC16(base + (uint32_t)(A_HALVES + row * AST + c * 8) * 2,
                       pB + (size_t)row * SS + j0 + c * 8);
        }
        CP_COMMIT();
    };

    load_stage(0);

    for (int kt = 0; kt < kc; kt++) {
        if (kt + 1 < kc) {
            load_stage(kt + 1);
            CP_WAIT(1);
        } else {
            CP_WAIT(0);
        }
        __syncthreads();

        const uint32_t abase = sbase + (uint32_t)((kt & 1) * BUF_HALVES) * 2;
        const uint32_t bbase = abase + (uint32_t)A_HALVES * 2;

#pragma unroll
        for (int ks = 0; ks < BK; ks += 16) {
            uint32_t afr[4][4];
#pragma unroll
            for (int mf = 0; mf < 4; mf++) {
                uint32_t ad = abase + (uint32_t)(((wm * 64 + mf * 16) * AST + ks) + a_off) * 2;
                LDSM4(afr[mf][0], afr[mf][1], afr[mf][2], afr[mf][3], ad);
            }
            uint32_t bfr[4][2];
#pragma unroll
            for (int np = 0; np < 2; np++) {
                uint32_t bd = bbase + (uint32_t)(((wn * 32 + np * 16) * AST + ks) + b_off) * 2;
                LDSM4(bfr[2 * np][0], bfr[2 * np][1],
                      bfr[2 * np + 1][0], bfr[2 * np + 1][1], bd);
            }
#pragma unroll
            for (int mf = 0; mf < 4; mf++) {
#pragma unroll
                for (int nf = 0; nf < 4; nf++) {
                    asm volatile(
                        "mma.sync.aligned.m16n8k16.row.col.f32.f16.f16.f32 "
                        "{%0,%1,%2,%3}, {%4,%5,%6,%7}, {%8,%9}, {%0,%1,%2,%3};"
                        : "+f"(acc[mf][nf][0]), "+f"(acc[mf][nf][1]),
                          "+f"(acc[mf][nf][2]), "+f"(acc[mf][nf][3])
                        : "r"(afr[mf][0]), "r"(afr[mf][1]),
                          "r"(afr[mf][2]), "r"(afr[mf][3]),
                        "r"(bfr[nf][0]), "r"(bfr[nf][1]));
                }
            }
        }
        __syncthreads();
    }

    const int* idxp = g_idx + b * SS;
#pragma unroll
    for (int mf = 0; mf < 4; mf++) {
        int r0 = ti + wm * 64 + mf * 16 + gid;
        int r1 = r0 + 8;
        int ig0 = (r0 < nI) ? idxp[r0] : -1;
        int ig1 = (r1 < nI) ? idxp[r1] : -1;
#pragma unroll
        for (int nf = 0; nf < 4; nf++) {
            int col = td + wn * 32 + nf * 8 + tig * 2;
            if (ig0 >= 0)
                *(float2*)(out + (size_t)ig0 * (BB * DD) + (size_t)b * DD + col) =
                    make_float2(acc[mf][nf][0], acc[mf][nf][1]);
            if (ig1 >= 0)
                *(float2*)(out + (size_t)ig1 * (BB * DD) + (size_t)b * DD + col) =
                    make_float2(acc[mf][nf][2], acc[mf][nf][3]);
        }
    }
}

// ---------------------------------------------------------------------------
// Launch: 4-way per-batch-group pipeline (3 streams + 4 events, R10 budget).
// ---------------------------------------------------------------------------
extern "C" void kernel_launch(void* const* d_in, const int* in_sizes, int n_in,
                              void* d_out, int out_size) {
    const float* x    = (const float*)d_in[0];
    const float* pe   = (const float*)d_in[2];
    const void*  mask = d_in[3];
    const float* W    = (const float*)d_in[4];
    const float* bias = (const float*)d_in[5];
    float*       out  = (float*)d_out;

    cudaFuncSetAttribute(gemm_fp16_kernel,
                         cudaFuncAttributeMaxDynamicSharedMemorySize, GEMM_SMEM);

    cudaStream_t sx[3];
    cudaEvent_t  ev[3];
    cudaEvent_t  e0;
    cudaEventCreateWithFlags(&e0, cudaEventDisableTiming);
    for (int g = 0; g < 3; g++) {
        cudaStreamCreateWithFlags(&sx[g], cudaStreamNonBlocking);
        cudaEventCreateWithFlags(&ev[g], cudaEventDisableTiming);
    }

    mask_kernel<<<BB, 1024>>>(mask);
    cudaEventRecord(e0, 0);

    for (int g = 0; g < NGRP; g++) {
        int b0 = g * GB;
        cudaStream_t s = (g == 0) ? (cudaStream_t)0 : sx[g - 1];
        if (g != 0) cudaStreamWaitEvent(s, e0, 0);

        dim3 pgrid(SS, GB);
        probpred_kernel<<<pgrid, 256, 0, s>>>(x, W, bias, b0);

        dim3 g2(SS / 64, DD / 64, GB);
        gather_kernel<<<g2, 256, 0, s>>>(pe, b0);

        dim3 ggrid(DD / NT, SS / MT, GB);
        gemm_fp16_kernel<<<ggrid, 256, GEMM_SMEM, s>>>(out, b0);

        dim3 zgrid(SS / 4, GB);
        zerofill_kernel<<<zgrid, 1024, 0, s>>>(out, b0);

        if (g != 0) cudaEventRecord(ev[g - 1], s);
    }
    for (int g = 0; g < 3; g++) cudaStreamWaitEvent(0, ev[g], 0);

    cudaEventDestroy(e0);
    for (int g = 0; g < 3; g++) {
        cudaEventDestroy(ev[g]);
        cudaStreamDestroy(sx[g]);
    }
}